// round 14
// baseline (speedup 1.0000x reference)
#include <cuda_runtime.h>
#include <cuda_fp16.h>
#include <cstdint>
#include <math.h>

#define DIM   768
#define HEADS 12
#define HD    64
#define BS    32
#define NMM   256
#define NV    196
#define NA    60
#define NSRC  256            // NV + NA
#define MQ    (BS * NMM)     // 8192

// ---------------------------------------------------------------------------
// Scratch (static __device__ globals; allocation is forbidden)
// ---------------------------------------------------------------------------
__device__ float g_attn_fallback[(size_t)BS * HEADS * NMM * NSRC];

__device__ __half g_Axmm_hi[(size_t)MQ * DIM];
__device__ __half g_Axmm_lo[(size_t)MQ * DIM];
__device__ __half g_Asrc_hi[(size_t)MQ * DIM];
__device__ __half g_Asrc_lo[(size_t)MQ * DIM];
__device__ __half g_Qh [(size_t)MQ * DIM];
__device__ __half g_Ql [(size_t)MQ * DIM];
__device__ __half g_KVh[(size_t)MQ * 2 * DIM];
__device__ __half g_KVl[(size_t)MQ * 2 * DIM];
__device__ __half g_Oh [(size_t)MQ * DIM];
__device__ __half g_Ol [(size_t)MQ * DIM];
__device__ __half g_Wqt_hi [(size_t)DIM * DIM];
__device__ __half g_Wqt_lo [(size_t)DIM * DIM];
__device__ __half g_Wkvt_hi[(size_t)2 * DIM * DIM];
__device__ __half g_Wkvt_lo[(size_t)2 * DIM * DIM];
__device__ __half g_Wpt_hi [(size_t)DIM * DIM];
__device__ __half g_Wpt_lo [(size_t)DIM * DIM];

// ---------------------------------------------------------------------------
// helpers
// ---------------------------------------------------------------------------
__device__ __forceinline__ uint32_t smem_u32(const void* p) {
    uint32_t a;
    asm("{ .reg .u64 t; cvta.to.shared.u64 t, %1; cvt.u32.u64 %0, t; }" : "=r"(a) : "l"(p));
    return a;
}
__device__ __forceinline__ uint32_t pack_h2(__half a, __half b) {
    __half2 t = __halves2half2(a, b);
    return *reinterpret_cast<uint32_t*>(&t);
}
__device__ __forceinline__ void split2h(float a, float b, uint32_t& hi, uint32_t& lo) {
    __half ha = __float2half_rn(a), hb = __float2half_rn(b);
    hi = pack_h2(ha, hb);
    lo = pack_h2(__float2half_rn(a - __half2float(ha)),
                 __float2half_rn(b - __half2float(hb)));
}
__device__ __forceinline__ void cp_async16(uint32_t saddr, const void* gptr) {
    asm volatile("cp.async.cg.shared.global [%0], [%1], 16;" :: "r"(saddr), "l"(gptr));
}
__device__ __forceinline__ void cp_commit() { asm volatile("cp.async.commit_group;"); }
template<int N_>
__device__ __forceinline__ void cp_wait() { asm volatile("cp.async.wait_group %0;" :: "n"(N_)); }

// fp16 inputs, fp32 accumulator (rt ~16)
__device__ __forceinline__ void mma_f32(float* c, uint32_t a0, uint32_t a1,
                                        uint32_t a2, uint32_t a3,
                                        uint32_t b0, uint32_t b1) {
    asm volatile(
        "mma.sync.aligned.m16n8k16.row.col.f32.f16.f16.f32 "
        "{%0,%1,%2,%3}, {%4,%5,%6,%7}, {%8,%9}, {%0,%1,%2,%3};"
        : "+f"(c[0]), "+f"(c[1]), "+f"(c[2]), "+f"(c[3])
        : "r"(a0), "r"(a1), "r"(a2), "r"(a3), "r"(b0), "r"(b1));
}
// fp16 inputs, fp16 accumulator (rt ~8) — for small cross terms
__device__ __forceinline__ void mma_f16(uint32_t& c0, uint32_t& c1,
                                        uint32_t a0, uint32_t a1,
                                        uint32_t a2, uint32_t a3,
                                        uint32_t b0, uint32_t b1) {
    asm volatile(
        "mma.sync.aligned.m16n8k16.row.col.f16.f16.f16.f16 "
        "{%0,%1}, {%2,%3,%4,%5}, {%6,%7}, {%0,%1};"
        : "+r"(c0), "+r"(c1)
        : "r"(a0), "r"(a1), "r"(a2), "r"(a3), "r"(b0), "r"(b1));
}
__device__ __forceinline__ void fold2(float* c, uint32_t c0, uint32_t c1) {
    float2 f0 = __half22float2(*reinterpret_cast<__half2*>(&c0));
    float2 f1 = __half22float2(*reinterpret_cast<__half2*>(&c1));
    c[0] += f0.x; c[1] += f0.y; c[2] += f1.x; c[3] += f1.y;
}
__device__ __forceinline__ void ldmx4(uint32_t* r, uint32_t saddr) {
    asm volatile("ldmatrix.sync.aligned.m8n8.x4.shared.b16 {%0,%1,%2,%3}, [%4];"
                 : "=r"(r[0]), "=r"(r[1]), "=r"(r[2]), "=r"(r[3]) : "r"(saddr));
}
__device__ __forceinline__ void ldmx4t(uint32_t* r, uint32_t saddr) {
    asm volatile("ldmatrix.sync.aligned.m8n8.x4.trans.shared.b16 {%0,%1,%2,%3}, [%4];"
                 : "=r"(r[0]), "=r"(r[1]), "=r"(r[2]), "=r"(r[3]) : "r"(saddr));
}
__device__ __forceinline__ void st_cs_f2(float* p, float x, float y) {
    asm volatile("st.global.cs.v2.f32 [%0], {%1, %2};" :: "l"(p), "f"(x), "f"(y) : "memory");
}
__device__ __forceinline__ void split4h(float4 x, uint2& hi, uint2& lo) {
    uint32_t h0, l0, h1, l1;
    split2h(x.x, x.y, h0, l0);
    split2h(x.z, x.w, h1, l1);
    hi = make_uint2(h0, h1);
    lo = make_uint2(l0, l1);
}

// ---------------------------------------------------------------------------
// Merged conversion kernels: fp32 -> (hi, lo) fp16 split
// ---------------------------------------------------------------------------
__global__ void split_all_v4(const float4* __restrict__ xmm,
                             const float4* __restrict__ xv, const float4* __restrict__ xa,
                             uint2* __restrict__ xh, uint2* __restrict__ xl,
                             uint2* __restrict__ sh, uint2* __restrict__ sl) {
    const int D4 = DIM / 4;
    size_t n4 = (size_t)MQ * D4;
    if (blockIdx.y == 0) {
        for (size_t i = (size_t)blockIdx.x * blockDim.x + threadIdx.x; i < n4;
             i += (size_t)gridDim.x * blockDim.x) {
            uint2 H, L;
            split4h(xmm[i], H, L);
            xh[i] = H;
            xl[i] = L;
        }
    } else {
        for (size_t i = (size_t)blockIdx.x * blockDim.x + threadIdx.x; i < n4;
             i += (size_t)gridDim.x * blockDim.x) {
            size_t row = i / D4, cg = i % D4;
            int b = (int)(row >> 8), t = (int)(row & 255);
            float4 x = (t < NV) ? xv[((size_t)b * NV + t) * D4 + cg]
                                : xa[((size_t)b * NA + (t - NV)) * D4 + cg];
            uint2 H, L;
            split4h(x, H, L);
            sh[i] = H;
            sl[i] = L;
        }
    }
}

// z selects weight matrix: 0 = Wq, 1 = Wkv, 2 = Wproj
__global__ void transpose_split_all(
    const float* __restrict__ Wq,  __half* __restrict__ Qh_, __half* __restrict__ Ql_,
    const float* __restrict__ Wkv, __half* __restrict__ Kh_, __half* __restrict__ Kl_,
    const float* __restrict__ Wp,  __half* __restrict__ Ph_, __half* __restrict__ Pl_)
{
    __shared__ float tile[32][33];
    int z = blockIdx.z;
    int N = (z == 1) ? 2 * DIM : DIM;
    if (blockIdx.x * 32 >= N) return;
    const float* W = (z == 0) ? Wq : (z == 1) ? Wkv : Wp;
    __half* Thi = (z == 0) ? Qh_ : (z == 1) ? Kh_ : Ph_;
    __half* Tlo = (z == 0) ? Ql_ : (z == 1) ? Kl_ : Pl_;

    int n0 = blockIdx.x * 32, k0 = blockIdx.y * 32;
    int tx = threadIdx.x, ty = threadIdx.y;     // (32, 8)
#pragma unroll
    for (int j = 0; j < 32; j += 8)
        tile[ty + j][tx] = W[(size_t)(k0 + ty + j) * N + (n0 + tx)];
    __syncthreads();
#pragma unroll
    for (int j = 0; j < 32; j += 8) {
        float v = tile[tx][ty + j];
        __half h = __float2half_rn(v);
        size_t o = (size_t)(n0 + ty + j) * DIM + (k0 + tx);   // K == DIM always
        Thi[o] = h;
        Tlo[o] = __float2half_rn(v - __half2float(h));
    }
}

// ---------------------------------------------------------------------------
// HMMA split-fp16 GEMM: C[M,N] = A[M,K] @ Bt[N,K]^T ; K=768 compile-time.
// Main term fp32-accum; cross terms fp16-accum, folded per k-step.
// CTA 128x128, 8 warps 64x32, K-chunk 32, double buffer, single sync/chunk.
// ---------------------------------------------------------------------------
#define CK       32
#define GK       768
#define SROW     40
#define TILE_BF  (128 * SROW)
#define ST_ELEMS (4 * TILE_BF)
#define GEMM_SMEM (2 * ST_ELEMS * 2)        // 81920 bytes

template<bool SPLIT, int NN>
__global__ void __launch_bounds__(256, 2) gemm_fp16s(
    const __half* __restrict__ Ahi, const __half* __restrict__ Alo,
    const __half* __restrict__ Bhi, const __half* __restrict__ Blo,
    float* __restrict__ C, __half* __restrict__ Chi, __half* __restrict__ Clo,
    const float* __restrict__ bias)
{
    extern __shared__ __align__(16) __half sm[];
    const int tid  = threadIdx.x;
    const int wid  = tid >> 5;
    const int lane = tid & 31;
    const int wm   = (wid >> 2) * 64;
    const int wn   = (wid & 3) * 32;
    const int m0   = blockIdx.y * 128;
    const int n0   = blockIdx.x * 128;
    constexpr int NC = GK / CK;             // 24

    const int lr = lane >> 2;
    const int lc = (lane & 3) * 2;

    const int arow = (lane & 7) + ((lane >> 3) & 1) * 8;
    const int akof = (lane >> 4) * 8;
    const int brow = (lane & 7) + ((lane >> 4) << 3);
    const int bkof = ((lane >> 3) & 1) * 8;

    float acc[4][4][4];
#pragma unroll
    for (int i = 0; i < 4; i++)
#pragma unroll
        for (int j = 0; j < 4; j++)
#pragma unroll
            for (int v = 0; v < 4; v++) acc[i][j][v] = 0.f;

    uint32_t smb = smem_u32(sm);
    const uint32_t offAh = (uint32_t)(0 * TILE_BF + (wm + arow) * SROW + akof) * 2;
    const uint32_t offAl = (uint32_t)(1 * TILE_BF + (wm + arow) * SROW + akof) * 2;
    const uint32_t offBh = (uint32_t)(2 * TILE_BF + (wn + brow) * SROW + bkof) * 2;
    const uint32_t offBl = (uint32_t)(3 * TILE_BF + (wn + brow) * SROW + bkof) * 2;

    auto load_chunk = [&](int c, int s) {
        uint32_t base = smb + (uint32_t)s * ST_ELEMS * 2;
        int k0 = c * CK;
#pragma unroll
        for (int it = 0; it < 2; it++) {
            int e   = tid + it * 256;
            int r   = e >> 2, seg = e & 3;
            uint32_t doff = (uint32_t)(r * SROW + seg * 8) * 2;
            size_t  goffA = (size_t)(m0 + r) * GK + k0 + seg * 8;
            size_t  goffB = (size_t)(n0 + r) * GK + k0 + seg * 8;
            cp_async16(base + 0 * TILE_BF * 2 + doff, Ahi + goffA);
            cp_async16(base + 1 * TILE_BF * 2 + doff, Alo + goffA);
            cp_async16(base + 2 * TILE_BF * 2 + doff, Bhi + goffB);
            cp_async16(base + 3 * TILE_BF * 2 + doff, Blo + goffB);
        }
        cp_commit();
    };

    load_chunk(0, 0);

#pragma unroll 2
    for (int c = 0; c < NC; c++) {
        int s = c & 1;
        cp_wait<0>();          // chunk c fully landed (only group outstanding)
        __syncthreads();       // single barrier per chunk
        if (c + 1 < NC) load_chunk(c + 1, (c + 1) & 1);   // into buffer freed at c-1

        uint32_t stg = smb + (uint32_t)s * ST_ELEMS * 2;

#pragma unroll
        for (int ks = 0; ks < 2; ks++) {
            uint32_t kbb = (uint32_t)(ks * 16) * 2;
            uint32_t bh[4][2], bl[4][2];
#pragma unroll
            for (int p = 0; p < 2; p++) {
                uint32_t t4[4];
                ldmx4(t4, stg + offBh + kbb + (uint32_t)(p * 16 * SROW) * 2);
                bh[2 * p][0] = t4[0]; bh[2 * p][1] = t4[1];
                bh[2 * p + 1][0] = t4[2]; bh[2 * p + 1][1] = t4[3];
                ldmx4(t4, stg + offBl + kbb + (uint32_t)(p * 16 * SROW) * 2);
                bl[2 * p][0] = t4[0]; bl[2 * p][1] = t4[1];
                bl[2 * p + 1][0] = t4[2]; bl[2 * p + 1][1] = t4[3];
            }
#pragma unroll
            for (int mt = 0; mt < 4; mt++) {
                uint32_t ah[4], al[4];
                ldmx4(ah, stg + offAh + kbb + (uint32_t)(mt * 16 * SROW) * 2);
                ldmx4(al, stg + offAl + kbb + (uint32_t)(mt * 16 * SROW) * 2);
#pragma unroll
                for (int nt = 0; nt < 4; nt++) {
                    uint32_t c0 = 0, c1 = 0;
                    mma_f16(c0, c1, ah[0], ah[1], ah[2], ah[3], bl[nt][0], bl[nt][1]);
                    mma_f16(c0, c1, al[0], al[1], al[2], al[3], bh[nt][0], bh[nt][1]);
                    mma_f32(acc[mt][nt], ah[0], ah[1], ah[2], ah[3], bh[nt][0], bh[nt][1]);
                    fold2(acc[mt][nt], c0, c1);
                }
            }
        }
    }

#pragma unroll
    for (int mt = 0; mt < 4; mt++) {
        int r0 = m0 + wm + mt * 16 + lr;
#pragma unroll
        for (int nt = 0; nt < 4; nt++) {
            int cc = n0 + wn + nt * 8 + lc;
            if (SPLIT) {
                uint32_t h0, l0, h1, l1;
                split2h(acc[mt][nt][0], acc[mt][nt][1], h0, l0);
                split2h(acc[mt][nt][2], acc[mt][nt][3], h1, l1);
                *(uint32_t*)(Chi + (size_t)r0 * NN + cc)       = h0;
                *(uint32_t*)(Clo + (size_t)r0 * NN + cc)       = l0;
                *(uint32_t*)(Chi + (size_t)(r0 + 8) * NN + cc) = h1;
                *(uint32_t*)(Clo + (size_t)(r0 + 8) * NN + cc) = l1;
            } else {
                float b0 = bias ? bias[cc]     : 0.f;
                float b1 = bias ? bias[cc + 1] : 0.f;
                float* p0 = C + (size_t)r0 * NN + cc;
                float* p1 = C + (size_t)(r0 + 8) * NN + cc;
                p0[0] = acc[mt][nt][0] + b0;
                p0[1] = acc[mt][nt][1] + b1;
                p1[0] = acc[mt][nt][2] + b0;
                p1[1] = acc[mt][nt][3] + b1;
            }
        }
    }
}

// ---------------------------------------------------------------------------
// HMMA flash-style attention, chunked cp.async pipeline, fp16 split,
// mixed-precision accumulation (main fp32, cross fp16 folded).
// CTA = (q-tile 128, h, b), 256 thr (8 warps).
// ---------------------------------------------------------------------------
#define QSTR 72
#define AT_QH   0
#define AT_QL   (128 * QSTR)
#define AT_BUF0 (2 * 128 * QSTR)
#define AT_BUF1 (AT_BUF0 + 2 * 128 * QSTR)
#define AT_LOFF (128 * QSTR)
#define AT_SMEM_ELE (AT_BUF1 + 2 * 128 * QSTR)   // 55296 halves
#define AT_SMEM_BYTES (AT_SMEM_ELE * 2)          // 110592

__global__ void __launch_bounds__(256) attn_mma(
    const __half* __restrict__ Qhi, const __half* __restrict__ Qlo,
    const __half* __restrict__ KVhi, const __half* __restrict__ KVlo,
    float* __restrict__ attn,
    __half* __restrict__ Ohi, __half* __restrict__ Olo)
{
    extern __shared__ __align__(16) __half asm_[];
    const int tid  = threadIdx.x;
    const int wid  = tid >> 5;
    const int lane = tid & 31;
    const int lr   = lane >> 2;
    const int lc   = lane & 3;
    const int b    = blockIdx.z;
    const int h    = blockIdx.y;
    const int q0   = blockIdx.x * 128;

    const int arow = (lane & 7) + ((lane >> 3) & 1) * 8;
    const int akof = (lane >> 4) * 8;
    const int brow = (lane & 7) + ((lane >> 4) << 3);
    const int bkof = ((lane >> 3) & 1) * 8;

    uint32_t smb = smem_u32(asm_);

    auto load_kv = [&](int key0, int is_v, uint32_t bufoff) {
        const __half* sh = KVhi + ((size_t)b * NSRC + key0) * (2 * DIM) + h * HD + is_v * DIM;
        const __half* sl = KVlo + ((size_t)b * NSRC + key0) * (2 * DIM) + h * HD + is_v * DIM;
#pragma unroll
        for (int it = 0; it < 4; it++) {
            int e = tid + it * 256;
            int r = e >> 3, s = e & 7;
            size_t go = (size_t)r * (2 * DIM) + s * 8;
            uint32_t doff = (uint32_t)(r * QSTR + s * 8) * 2;
            cp_async16(smb + (bufoff * 2) + doff, sh + go);
            cp_async16(smb + ((bufoff + AT_LOFF) * 2) + doff, sl + go);
        }
        cp_commit();
    };

    // ---- prologue: async K0, K1; regular Q ----
    load_kv(0,   0, AT_BUF0);
    load_kv(128, 0, AT_BUF1);
    {
        const __half* Qgh = Qhi + ((size_t)(b * NMM + q0)) * DIM + h * HD;
        const __half* Qgl = Qlo + ((size_t)(b * NMM + q0)) * DIM + h * HD;
#pragma unroll
        for (int it = 0; it < 4; it++) {
            int e = tid + it * 256;
            int r = e >> 3, s = e & 7;
            *(uint4*)&asm_[AT_QH + r * QSTR + s * 8] = *(const uint4*)(Qgh + (size_t)r * DIM + s * 8);
            *(uint4*)&asm_[AT_QL + r * QSTR + s * 8] = *(const uint4*)(Qgl + (size_t)r * DIM + s * 8);
        }
    }
    cp_wait<1>();
    __syncthreads();

    // ---- Q fragments ----
    uint32_t qh[4][4], ql[4][4];
    {
        uint32_t qoff = smb + (uint32_t)((wid * 16 + arow) * QSTR + akof) * 2;
#pragma unroll
        for (int kt = 0; kt < 4; kt++) {
            ldmx4(qh[kt], qoff + (uint32_t)(AT_QH * 2) + kt * 32);
            ldmx4(ql[kt], qoff + (uint32_t)(AT_QL * 2) + kt * 32);
        }
    }

    float acc[32][4];
#pragma unroll
    for (int t = 0; t < 32; t++)
#pragma unroll
        for (int v = 0; v < 4; v++) acc[t][v] = 0.f;

    // S over one 128-key chunk; cross terms in fp16 acc, folded per key-pair
    auto s_chunk = [&](uint32_t bufoff, int accb) {
        uint32_t kb = smb + (uint32_t)(bufoff + brow * QSTR + bkof) * 2;
#pragma unroll
        for (int p = 0; p < 8; p++) {
            uint32_t prow = kb + (uint32_t)(p * 16 * QSTR) * 2;
            float* a0 = acc[accb + 2 * p];
            float* a1 = acc[accb + 2 * p + 1];
            uint32_t c00 = 0, c01 = 0, c10 = 0, c11 = 0;
#pragma unroll
            for (int kt = 0; kt < 4; kt++) {
                uint32_t kh4[4], kl4[4];
                ldmx4(kh4, prow + kt * 32);
                ldmx4(kl4, prow + (uint32_t)(AT_LOFF * 2) + kt * 32);
                mma_f16(c00, c01, qh[kt][0], qh[kt][1], qh[kt][2], qh[kt][3], kl4[0], kl4[1]);
                mma_f16(c00, c01, ql[kt][0], ql[kt][1], ql[kt][2], ql[kt][3], kh4[0], kh4[1]);
                mma_f32(a0, qh[kt][0], qh[kt][1], qh[kt][2], qh[kt][3], kh4[0], kh4[1]);
                mma_f16(c10, c11, qh[kt][0], qh[kt][1], qh[kt][2], qh[kt][3], kl4[2], kl4[3]);
                mma_f16(c10, c11, ql[kt][0], ql[kt][1], ql[kt][2], ql[kt][3], kh4[2], kh4[3]);
                mma_f32(a1, qh[kt][0], qh[kt][1], qh[kt][2], qh[kt][3], kh4[2], kh4[3]);
            }
            fold2(a0, c00, c01);
            fold2(a1, c10, c11);
        }
    };

    s_chunk(AT_BUF0, 0);
    __syncthreads();
    load_kv(0, 1, AT_BUF0);        // V0 -> buf0
    cp_wait<1>();                  // K1 done
    __syncthreads();
    s_chunk(AT_BUF1, 16);
    __syncthreads();
    load_kv(128, 1, AT_BUF1);      // V1 -> buf1

    // ---- softmax ----
    const float scale = 0.125f;
    float mx0 = -1e30f, mx1 = -1e30f;
#pragma unroll
    for (int t = 0; t < 32; t++) {
        mx0 = fmaxf(mx0, fmaxf(acc[t][0], acc[t][1]));
        mx1 = fmaxf(mx1, fmaxf(acc[t][2], acc[t][3]));
    }
    mx0 = fmaxf(mx0, __shfl_xor_sync(0xffffffffu, mx0, 1));
    mx0 = fmaxf(mx0, __shfl_xor_sync(0xffffffffu, mx0, 2));
    mx1 = fmaxf(mx1, __shfl_xor_sync(0xffffffffu, mx1, 1));
    mx1 = fmaxf(mx1, __shfl_xor_sync(0xffffffffu, mx1, 2));
    float s0 = 0.f, s1 = 0.f;
#pragma unroll
    for (int t = 0; t < 32; t++) {
        acc[t][0] = __expf((acc[t][0] - mx0) * scale); s0 += acc[t][0];
        acc[t][1] = __expf((acc[t][1] - mx0) * scale); s0 += acc[t][1];
        acc[t][2] = __expf((acc[t][2] - mx1) * scale); s1 += acc[t][2];
        acc[t][3] = __expf((acc[t][3] - mx1) * scale); s1 += acc[t][3];
    }
    s0 += __shfl_xor_sync(0xffffffffu, s0, 1);
    s0 += __shfl_xor_sync(0xffffffffu, s0, 2);
    s1 += __shfl_xor_sync(0xffffffffu, s1, 1);
    s1 += __shfl_xor_sync(0xffffffffu, s1, 2);
    float i0 = 1.f / s0, i1 = 1.f / s1;
#pragma unroll
    for (int t = 0; t < 32; t++) {
        acc[t][0] *= i0; acc[t][1] *= i0; acc[t][2] *= i1; acc[t][3] *= i1;
    }

    // ---- write attn probs (fp32, streaming) ----
    {
        float* ar0 = attn + ((size_t)((b * HEADS + h) * NMM) + q0 + wid * 16 + lr) * NSRC + 2 * lc;
        float* ar1 = ar0 + (size_t)8 * NSRC;
#pragma unroll
        for (int t = 0; t < 32; t++) {
            st_cs_f2(ar0 + t * 8, acc[t][0], acc[t][1]);
            st_cs_f2(ar1 + t * 8, acc[t][2], acc[t][3]);
        }
    }

    // ---- P -> fp16 hi/lo A-fragments ----
    uint32_t ph[16][4], pl[16][4];
#pragma unroll
    for (int t = 0; t < 16; t++) {
        split2h(acc[2 * t][0],     acc[2 * t][1],     ph[t][0], pl[t][0]);
        split2h(acc[2 * t][2],     acc[2 * t][3],     ph[t][1], pl[t][1]);
        split2h(acc[2 * t + 1][0], acc[2 * t + 1][1], ph[t][2], pl[t][2]);
        split2h(acc[2 * t + 1][2], acc[2 * t + 1][3], ph[t][3], pl[t][3]);
    }

    // ---- O = P V ; cross terms fp16-acc carried across both chunks ----
    float oacc[8][4];
    uint32_t oc16[8][2];
#pragma unroll
    for (int nd = 0; nd < 8; nd++) {
        oc16[nd][0] = 0; oc16[nd][1] = 0;
#pragma unroll
        for (int v = 0; v < 4; v++) oacc[nd][v] = 0.f;
    }

    auto pv_chunk = [&](uint32_t bufoff, int ktb) {
        uint32_t vbase = smb + (uint32_t)(bufoff + (lane & 15) * QSTR + (lane >> 4) * 8) * 2;
#pragma unroll
        for (int ktl = 0; ktl < 8; ktl++) {
            int kt = ktb + ktl;
            uint32_t vrow = vbase + (uint32_t)(ktl * 16 * QSTR) * 2;
#pragma unroll
            for (int ndp = 0; ndp < 4; ndp++) {
                uint32_t vh4[4], vl4[4];
                ldmx4t(vh4, vrow + ndp * 32);
                ldmx4t(vl4, vrow + (uint32_t)(AT_LOFF * 2) + ndp * 32);
                mma_f16(oc16[2 * ndp][0], oc16[2 * ndp][1],
                        ph[kt][0], ph[kt][1], ph[kt][2], ph[kt][3], vl4[0], vl4[1]);
                mma_f16(oc16[2 * ndp][0], oc16[2 * ndp][1],
                        pl[kt][0], pl[kt][1], pl[kt][2], pl[kt][3], vh4[0], vh4[1]);
                mma_f32(oacc[2 * ndp], ph[kt][0], ph[kt][1], ph[kt][2], ph[kt][3], vh4[0], vh4[1]);
                mma_f16(oc16[2 * ndp + 1][0], oc16[2 * ndp + 1][1],
                        ph[kt][0], ph[kt][1], ph[kt][2], ph[kt][3], vl4[2], vl4[3]);
                mma_f16(oc16[2 * ndp + 1][0], oc16[2 * ndp + 1][1],
                        pl[kt][0], pl[kt][1], pl[kt][2], pl[kt][3], vh4[2], vh4[3]);
                mma_f32(oacc[2 * ndp + 1], ph[kt][0], ph[kt][1], ph[kt][2], ph[kt][3], vh4[2], vh4[3]);
            }
        }
    };

    cp_wait<1>();                  // V0 arrived
    __syncthreads();
    pv_chunk(AT_BUF0, 0);
    cp_wait<0>();                  // V1 arrived
    __syncthreads();
    pv_chunk(AT_BUF1, 8);

#pragma unroll
    for (int nd = 0; nd < 8; nd++) fold2(oacc[nd], oc16[nd][0], oc16[nd][1]);

    // ---- write O as fp16 hi/lo ----
    {
        size_t row0 = (size_t)(b * NMM + q0 + wid * 16 + lr);
        __half* oh0 = Ohi + row0 * DIM + h * HD + 2 * lc;
        __half* ol0 = Olo + row0 * DIM + h * HD + 2 * lc;
        __half* oh1 = oh0 + (size_t)8 * DIM;
        __half* ol1 = ol0 + (size_t)8 * DIM;
#pragma unroll
        for (int nd = 0; nd < 8; nd++) {
            uint32_t hh, ll;
            split2h(oacc[nd][0], oacc[nd][1], hh, ll);
            *(uint32_t*)(oh0 + nd * 8) = hh;
            *(uint32_t*)(ol0 + nd * 8) = ll;
            split2h(oacc[nd][2], oacc[nd][3], hh, ll);
            *(uint32_t*)(oh1 + nd * 8) = hh;
            *(uint32_t*)(ol1 + nd * 8) = ll;
        }
    }
}

// ---------------------------------------------------------------------------
extern "C" void kernel_launch(void* const* d_in, const int* in_sizes, int n_in,
                              void* d_out, int out_size)
{
    const float* xmm   = (const float*)d_in[0];
    const float* xv    = (const float*)d_in[1];
    const float* xa    = (const float*)d_in[2];
    const float* Wq    = (const float*)d_in[3];
    const float* Wkv   = (const float*)d_in[4];
    const float* Wproj = (const float*)d_in[5];
    const float* bproj = (const float*)d_in[6];

    float* out = (float*)d_out;

    float* attn_fb;
    cudaGetSymbolAddress((void**)&attn_fb, g_attn_fallback);

    __half *Axh, *Axl, *Ash, *Asl;
    __half *Qh, *Ql, *KVh, *KVl, *Oh, *Ol;
    __half *Wqh, *Wql, *Wkh, *Wkl, *Wph, *Wpl;
    cudaGetSymbolAddress((void**)&Axh, g_Axmm_hi);
    cudaGetSymbolAddress((void**)&Axl, g_Axmm_lo);
    cudaGetSymbolAddress((void**)&Ash, g_Asrc_hi);
    cudaGetSymbolAddress((void**)&Asl, g_Asrc_lo);
    cudaGetSymbolAddress((void**)&Qh,  g_Qh);
    cudaGetSymbolAddress((void**)&Ql,  g_Ql);
    cudaGetSymbolAddress((void**)&KVh, g_KVh);
    cudaGetSymbolAddress((void**)&KVl, g_KVl);
    cudaGetSymbolAddress((void**)&Oh,  g_Oh);
    cudaGetSymbolAddress((void**)&Ol,  g_Ol);
    cudaGetSymbolAddress((void**)&Wqh, g_Wqt_hi);
    cudaGetSymbolAddress((void**)&Wql, g_Wqt_lo);
    cudaGetSymbolAddress((void**)&Wkh, g_Wkvt_hi);
    cudaGetSymbolAddress((void**)&Wkl, g_Wkvt_lo);
    cudaGetSymbolAddress((void**)&Wph, g_Wpt_hi);
    cudaGetSymbolAddress((void**)&Wpl, g_Wpt_lo);

    const size_t out_elems  = (size_t)MQ * DIM;
    const size_t attn_elems = (size_t)BS * HEADS * NMM * NSRC;
    float* attn_out = ((size_t)out_size >= out_elems + attn_elems)
                        ? out + out_elems : attn_fb;

    cudaFuncSetAttribute((const void*)gemm_fp16s<true, DIM>,
                         cudaFuncAttributeMaxDynamicSharedMemorySize, GEMM_SMEM);
    cudaFuncSetAttribute((const void*)gemm_fp16s<true, 2 * DIM>,
                         cudaFuncAttributeMaxDynamicSharedMemorySize, GEMM_SMEM);
    cudaFuncSetAttribute((const void*)gemm_fp16s<false, DIM>,
                         cudaFuncAttributeMaxDynamicSharedMemorySize, GEMM_SMEM);
    cudaFuncSetAttribute(attn_mma, cudaFuncAttributeMaxDynamicSharedMemorySize, AT_SMEM_BYTES);

    // --- conversions ---
    {
        dim3 bb(32, 8);
        transpose_split_all<<<dim3(2 * DIM / 32, DIM / 32, 3), bb>>>(
            Wq, Wqh, Wql, Wkv, Wkh, Wkl, Wproj, Wph, Wpl);
    }
    split_all_v4<<<dim3(1024, 2), 256>>>((const float4*)xmm,
                                         (const float4*)xv, (const float4*)xa,
                                         (uint2*)Axh, (uint2*)Axl,
                                         (uint2*)Ash, (uint2*)Asl);

    // --- Q = xmm @ Wq  -> fp16 hi/lo ---
    gemm_fp16s<true, DIM><<<dim3(DIM / 128, MQ / 128), 256, GEMM_SMEM>>>(
        Axh, Axl, Wqh, Wql, nullptr, Qh, Ql, nullptr);
    // --- KV = concat(xv,xa) @ Wkv -> fp16 hi/lo ---
    gemm_fp16s<true, 2 * DIM><<<dim3(2 * DIM / 128, MQ / 128), 256, GEMM_SMEM>>>(
        Ash, Asl, Wkh, Wkl, nullptr, KVh, KVl, nullptr);
    // --- attention ---
    attn_mma<<<dim3(NMM / 128, HEADS, BS), 256, AT_SMEM_BYTES>>>(
        Qh, Ql, KVh, KVl, attn_out, Oh, Ol);
    // --- out = O @ Wproj + bproj (fp32) ---
    gemm_fp16s<false, DIM><<<dim3(DIM / 128, MQ / 128), 256, GEMM_SMEM>>>(
        Oh, Ol, Wph, Wpl, out, nullptr, nullptr, bproj);
}

// round 15
// speedup vs baseline: 1.5858x; 1.5858x over previous
#include <cuda_runtime.h>
#include <cuda_fp16.h>
#include <cstdint>
#include <math.h>

#define DIM   768
#define HEADS 12
#define HD    64
#define BS    32
#define NMM   256
#define NV    196
#define NA    60
#define NSRC  256            // NV + NA
#define MQ    (BS * NMM)     // 8192

// ---------------------------------------------------------------------------
// Scratch (static __device__ globals; allocation is forbidden)
// ---------------------------------------------------------------------------
__device__ float g_attn_fallback[(size_t)BS * HEADS * NMM * NSRC];

__device__ __half g_Axmm_hi[(size_t)MQ * DIM];
__device__ __half g_Axmm_lo[(size_t)MQ * DIM];
__device__ __half g_Asrc_hi[(size_t)MQ * DIM];
__device__ __half g_Asrc_lo[(size_t)MQ * DIM];
__device__ __half g_Qh [(size_t)MQ * DIM];
__device__ __half g_Ql [(size_t)MQ * DIM];
__device__ __half g_KVh[(size_t)MQ * 2 * DIM];
__device__ __half g_KVl[(size_t)MQ * 2 * DIM];
__device__ __half g_Oh [(size_t)MQ * DIM];
__device__ __half g_Ol [(size_t)MQ * DIM];
__device__ __half g_Wqt [(size_t)DIM * DIM];
__device__ __half g_Wkvt[(size_t)2 * DIM * DIM];
__device__ __half g_Wpt [(size_t)DIM * DIM];

// ---------------------------------------------------------------------------
// helpers
// ---------------------------------------------------------------------------
__device__ __forceinline__ uint32_t smem_u32(const void* p) {
    uint32_t a;
    asm("{ .reg .u64 t; cvta.to.shared.u64 t, %1; cvt.u32.u64 %0, t; }" : "=r"(a) : "l"(p));
    return a;
}
__device__ __forceinline__ uint32_t pack_h2(__half a, __half b) {
    __half2 t = __halves2half2(a, b);
    return *reinterpret_cast<uint32_t*>(&t);
}
__device__ __forceinline__ void split2h(float a, float b, uint32_t& hi, uint32_t& lo) {
    __half ha = __float2half_rn(a), hb = __float2half_rn(b);
    hi = pack_h2(ha, hb);
    lo = pack_h2(__float2half_rn(a - __half2float(ha)),
                 __float2half_rn(b - __half2float(hb)));
}
__device__ __forceinline__ void cp_async16(uint32_t saddr, const void* gptr) {
    asm volatile("cp.async.cg.shared.global [%0], [%1], 16;" :: "r"(saddr), "l"(gptr));
}
__device__ __forceinline__ void cp_commit() { asm volatile("cp.async.commit_group;"); }
template<int N_>
__device__ __forceinline__ void cp_wait() { asm volatile("cp.async.wait_group %0;" :: "n"(N_)); }

// fp16 inputs, fp32 accumulator
__device__ __forceinline__ void mma_f32(float* c, uint32_t a0, uint32_t a1,
                                        uint32_t a2, uint32_t a3,
                                        uint32_t b0, uint32_t b1) {
    asm volatile(
        "mma.sync.aligned.m16n8k16.row.col.f32.f16.f16.f32 "
        "{%0,%1,%2,%3}, {%4,%5,%6,%7}, {%8,%9}, {%0,%1,%2,%3};"
        : "+f"(c[0]), "+f"(c[1]), "+f"(c[2]), "+f"(c[3])
        : "r"(a0), "r"(a1), "r"(a2), "r"(a3), "r"(b0), "r"(b1));
}
__device__ __forceinline__ void ldmx4(uint32_t* r, uint32_t saddr) {
    asm volatile("ldmatrix.sync.aligned.m8n8.x4.shared.b16 {%0,%1,%2,%3}, [%4];"
                 : "=r"(r[0]), "=r"(r[1]), "=r"(r[2]), "=r"(r[3]) : "r"(saddr));
}
__device__ __forceinline__ void ldmx4t(uint32_t* r, uint32_t saddr) {
    asm volatile("ldmatrix.sync.aligned.m8n8.x4.trans.shared.b16 {%0,%1,%2,%3}, [%4];"
                 : "=r"(r[0]), "=r"(r[1]), "=r"(r[2]), "=r"(r[3]) : "r"(saddr));
}
__device__ __forceinline__ void st_cs_f2(float* p, float x, float y) {
    asm volatile("st.global.cs.v2.f32 [%0], {%1, %2};" :: "l"(p), "f"(x), "f"(y) : "memory");
}
__device__ __forceinline__ void split4h(float4 x, uint2& hi, uint2& lo) {
    uint32_t h0, l0, h1, l1;
    split2h(x.x, x.y, h0, l0);
    split2h(x.z, x.w, h1, l1);
    hi = make_uint2(h0, h1);
    lo = make_uint2(l0, l1);
}

// ---------------------------------------------------------------------------
// Merged conversion kernels: activations fp32 -> (hi, lo) fp16 split
// ---------------------------------------------------------------------------
__global__ void split_all_v4(const float4* __restrict__ xmm,
                             const float4* __restrict__ xv, const float4* __restrict__ xa,
                             uint2* __restrict__ xh, uint2* __restrict__ xl,
                             uint2* __restrict__ sh, uint2* __restrict__ sl) {
    const int D4 = DIM / 4;
    size_t n4 = (size_t)MQ * D4;
    if (blockIdx.y == 0) {
        for (size_t i = (size_t)blockIdx.x * blockDim.x + threadIdx.x; i < n4;
             i += (size_t)gridDim.x * blockDim.x) {
            uint2 H, L;
            split4h(xmm[i], H, L);
            xh[i] = H;
            xl[i] = L;
        }
    } else {
        for (size_t i = (size_t)blockIdx.x * blockDim.x + threadIdx.x; i < n4;
             i += (size_t)gridDim.x * blockDim.x) {
            size_t row = i / D4, cg = i % D4;
            int b = (int)(row >> 8), t = (int)(row & 255);
            float4 x = (t < NV) ? xv[((size_t)b * NV + t) * D4 + cg]
                                : xa[((size_t)b * NA + (t - NV)) * D4 + cg];
            uint2 H, L;
            split4h(x, H, L);
            sh[i] = H;
            sl[i] = L;
        }
    }
}

// Weights fp32 -> transposed fp16 (hi only). z: 0 = Wq, 1 = Wkv, 2 = Wproj
__global__ void transpose_all(
    const float* __restrict__ Wq,  __half* __restrict__ Tq,
    const float* __restrict__ Wkv, __half* __restrict__ Tk,
    const float* __restrict__ Wp,  __half* __restrict__ Tp)
{
    __shared__ float tile[32][33];
    int z = blockIdx.z;
    int N = (z == 1) ? 2 * DIM : DIM;
    if (blockIdx.x * 32 >= N) return;
    const float* W = (z == 0) ? Wq : (z == 1) ? Wkv : Wp;
    __half* T = (z == 0) ? Tq : (z == 1) ? Tk : Tp;

    int n0 = blockIdx.x * 32, k0 = blockIdx.y * 32;
    int tx = threadIdx.x, ty = threadIdx.y;     // (32, 8)
#pragma unroll
    for (int j = 0; j < 32; j += 8)
        tile[ty + j][tx] = W[(size_t)(k0 + ty + j) * N + (n0 + tx)];
    __syncthreads();
#pragma unroll
    for (int j = 0; j < 32; j += 8) {
        float v = tile[tx][ty + j];
        T[(size_t)(n0 + ty + j) * DIM + (k0 + tx)] = __float2half_rn(v);
    }
}

// ---------------------------------------------------------------------------
// 2-product split-fp16 GEMM: C = (Ahi + Alo) @ Wt^T ; W plain fp16.
// CTA 128x128, 8 warps 64x32, K-chunk 32, double buffer.
// smem/stage: Ahi | Alo | B = 3 tiles of 128x40 halves.
// ---------------------------------------------------------------------------
#define CK       32
#define GK       768
#define SROW     40
#define TILE_BF  (128 * SROW)
#define ST_ELEMS (3 * TILE_BF)
#define GEMM_SMEM (2 * ST_ELEMS * 2)        // 61440 bytes

template<bool SPLIT, int NN>
__global__ void __launch_bounds__(256, 2) gemm_fp16s(
    const __half* __restrict__ Ahi, const __half* __restrict__ Alo,
    const __half* __restrict__ B,
    float* __restrict__ C, __half* __restrict__ Chi, __half* __restrict__ Clo,
    const float* __restrict__ bias)
{
    extern __shared__ __align__(16) __half sm[];
    const int tid  = threadIdx.x;
    const int wid  = tid >> 5;
    const int lane = tid & 31;
    const int wm   = (wid >> 2) * 64;
    const int wn   = (wid & 3) * 32;
    const int m0   = blockIdx.y * 128;
    const int n0   = blockIdx.x * 128;
    constexpr int NC = GK / CK;             // 24

    const int lr = lane >> 2;
    const int lc = (lane & 3) * 2;

    const int arow = (lane & 7) + ((lane >> 3) & 1) * 8;
    const int akof = (lane >> 4) * 8;
    const int brow = (lane & 7) + ((lane >> 4) << 3);
    const int bkof = ((lane >> 3) & 1) * 8;

    float acc[4][4][4];
#pragma unroll
    for (int i = 0; i < 4; i++)
#pragma unroll
        for (int j = 0; j < 4; j++)
#pragma unroll
            for (int v = 0; v < 4; v++) acc[i][j][v] = 0.f;

    uint32_t smb = smem_u32(sm);
    const uint32_t offAh = (uint32_t)(0 * TILE_BF + (wm + arow) * SROW + akof) * 2;
    const uint32_t offAl = (uint32_t)(1 * TILE_BF + (wm + arow) * SROW + akof) * 2;
    const uint32_t offB  = (uint32_t)(2 * TILE_BF + (wn + brow) * SROW + bkof) * 2;

    auto load_chunk = [&](int c, int s) {
        uint32_t base = smb + (uint32_t)s * ST_ELEMS * 2;
        int k0 = c * CK;
#pragma unroll
        for (int it = 0; it < 2; it++) {
            int e   = tid + it * 256;
            int r   = e >> 2, seg = e & 3;
            uint32_t doff = (uint32_t)(r * SROW + seg * 8) * 2;
            size_t  goffA = (size_t)(m0 + r) * GK + k0 + seg * 8;
            size_t  goffB = (size_t)(n0 + r) * GK + k0 + seg * 8;
            cp_async16(base + 0 * TILE_BF * 2 + doff, Ahi + goffA);
            cp_async16(base + 1 * TILE_BF * 2 + doff, Alo + goffA);
            cp_async16(base + 2 * TILE_BF * 2 + doff, B + goffB);
        }
        cp_commit();
    };

    load_chunk(0, 0);

#pragma unroll 2
    for (int c = 0; c < NC; c++) {
        int s = c & 1;
        if (c + 1 < NC) load_chunk(c + 1, (c + 1) & 1);
        if (c + 1 < NC) cp_wait<1>(); else cp_wait<0>();
        __syncthreads();

        uint32_t stg = smb + (uint32_t)s * ST_ELEMS * 2;

#pragma unroll
        for (int ks = 0; ks < 2; ks++) {
            uint32_t kbb = (uint32_t)(ks * 16) * 2;
            uint32_t bh[4][2];
#pragma unroll
            for (int p = 0; p < 2; p++) {
                uint32_t t4[4];
                ldmx4(t4, stg + offB + kbb + (uint32_t)(p * 16 * SROW) * 2);
                bh[2 * p][0] = t4[0]; bh[2 * p][1] = t4[1];
                bh[2 * p + 1][0] = t4[2]; bh[2 * p + 1][1] = t4[3];
            }
#pragma unroll
            for (int mt = 0; mt < 4; mt++) {
                uint32_t ah[4], al[4];
                ldmx4(ah, stg + offAh + kbb + (uint32_t)(mt * 16 * SROW) * 2);
                ldmx4(al, stg + offAl + kbb + (uint32_t)(mt * 16 * SROW) * 2);
#pragma unroll
                for (int nt = 0; nt < 4; nt++) {
                    mma_f32(acc[mt][nt], ah[0], ah[1], ah[2], ah[3], bh[nt][0], bh[nt][1]);
                    mma_f32(acc[mt][nt], al[0], al[1], al[2], al[3], bh[nt][0], bh[nt][1]);
                }
            }
        }
        __syncthreads();
    }

#pragma unroll
    for (int mt = 0; mt < 4; mt++) {
        int r0 = m0 + wm + mt * 16 + lr;
#pragma unroll
        for (int nt = 0; nt < 4; nt++) {
            int cc = n0 + wn + nt * 8 + lc;
            if (SPLIT) {
                uint32_t h0, l0, h1, l1;
                split2h(acc[mt][nt][0], acc[mt][nt][1], h0, l0);
                split2h(acc[mt][nt][2], acc[mt][nt][3], h1, l1);
                *(uint32_t*)(Chi + (size_t)r0 * NN + cc)       = h0;
                *(uint32_t*)(Clo + (size_t)r0 * NN + cc)       = l0;
                *(uint32_t*)(Chi + (size_t)(r0 + 8) * NN + cc) = h1;
                *(uint32_t*)(Clo + (size_t)(r0 + 8) * NN + cc) = l1;
            } else {
                float b0 = bias ? bias[cc]     : 0.f;
                float b1 = bias ? bias[cc + 1] : 0.f;
                float* p0 = C + (size_t)r0 * NN + cc;
                float* p1 = C + (size_t)(r0 + 8) * NN + cc;
                p0[0] = acc[mt][nt][0] + b0;
                p0[1] = acc[mt][nt][1] + b1;
                p1[0] = acc[mt][nt][2] + b0;
                p1[1] = acc[mt][nt][3] + b1;
            }
        }
    }
}

// ---------------------------------------------------------------------------
// HMMA flash-style attention, chunked cp.async pipeline, fp16 split,
// full 3-term, all fp32 accumulation (round-13 structure).
// CTA = (q-tile 128, h, b), 256 thr (8 warps).
// ---------------------------------------------------------------------------
#define QSTR 72
#define AT_QH   0
#define AT_QL   (128 * QSTR)
#define AT_BUF0 (2 * 128 * QSTR)
#define AT_BUF1 (AT_BUF0 + 2 * 128 * QSTR)
#define AT_LOFF (128 * QSTR)
#define AT_SMEM_ELE (AT_BUF1 + 2 * 128 * QSTR)   // 55296 halves
#define AT_SMEM_BYTES (AT_SMEM_ELE * 2)          // 110592

__global__ void __launch_bounds__(256) attn_mma(
    const __half* __restrict__ Qhi, const __half* __restrict__ Qlo,
    const __half* __restrict__ KVhi, const __half* __restrict__ KVlo,
    float* __restrict__ attn,
    __half* __restrict__ Ohi, __half* __restrict__ Olo)
{
    extern __shared__ __align__(16) __half asm_[];
    const int tid  = threadIdx.x;
    const int wid  = tid >> 5;
    const int lane = tid & 31;
    const int lr   = lane >> 2;
    const int lc   = lane & 3;
    const int b    = blockIdx.z;
    const int h    = blockIdx.y;
    const int q0   = blockIdx.x * 128;

    const int arow = (lane & 7) + ((lane >> 3) & 1) * 8;
    const int akof = (lane >> 4) * 8;
    const int brow = (lane & 7) + ((lane >> 4) << 3);
    const int bkof = ((lane >> 3) & 1) * 8;

    uint32_t smb = smem_u32(asm_);

    auto load_kv = [&](int key0, int is_v, uint32_t bufoff) {
        const __half* sh = KVhi + ((size_t)b * NSRC + key0) * (2 * DIM) + h * HD + is_v * DIM;
        const __half* sl = KVlo + ((size_t)b * NSRC + key0) * (2 * DIM) + h * HD + is_v * DIM;
#pragma unroll
        for (int it = 0; it < 4; it++) {
            int e = tid + it * 256;
            int r = e >> 3, s = e & 7;
            size_t go = (size_t)r * (2 * DIM) + s * 8;
            uint32_t doff = (uint32_t)(r * QSTR + s * 8) * 2;
            cp_async16(smb + (bufoff * 2) + doff, sh + go);
            cp_async16(smb + ((bufoff + AT_LOFF) * 2) + doff, sl + go);
        }
        cp_commit();
    };

    // ---- prologue: async K0, K1; regular Q ----
    load_kv(0,   0, AT_BUF0);
    load_kv(128, 0, AT_BUF1);
    {
        const __half* Qgh = Qhi + ((size_t)(b * NMM + q0)) * DIM + h * HD;
        const __half* Qgl = Qlo + ((size_t)(b * NMM + q0)) * DIM + h * HD;
#pragma unroll
        for (int it = 0; it < 4; it++) {
            int e = tid + it * 256;
            int r = e >> 3, s = e & 7;
            *(uint4*)&asm_[AT_QH + r * QSTR + s * 8] = *(const uint4*)(Qgh + (size_t)r * DIM + s * 8);
            *(uint4*)&asm_[AT_QL + r * QSTR + s * 8] = *(const uint4*)(Qgl + (size_t)r * DIM + s * 8);
        }
    }
    cp_wait<1>();
    __syncthreads();

    // ---- Q fragments ----
    uint32_t qh[4][4], ql[4][4];
    {
        uint32_t qoff = smb + (uint32_t)((wid * 16 + arow) * QSTR + akof) * 2;
#pragma unroll
        for (int kt = 0; kt < 4; kt++) {
            ldmx4(qh[kt], qoff + (uint32_t)(AT_QH * 2) + kt * 32);
            ldmx4(ql[kt], qoff + (uint32_t)(AT_QL * 2) + kt * 32);
        }
    }

    float acc[32][4];
#pragma unroll
    for (int t = 0; t < 32; t++)
#pragma unroll
        for (int v = 0; v < 4; v++) acc[t][v] = 0.f;

    auto s_chunk = [&](uint32_t bufoff, int accb) {
        uint32_t kb = smb + (uint32_t)(bufoff + brow * QSTR + bkof) * 2;
#pragma unroll
        for (int p = 0; p < 8; p++) {
            uint32_t prow = kb + (uint32_t)(p * 16 * QSTR) * 2;
            float* a0 = acc[accb + 2 * p];
            float* a1 = acc[accb + 2 * p + 1];
#pragma unroll
            for (int kt = 0; kt < 4; kt++) {
                uint32_t kh4[4], kl4[4];
                ldmx4(kh4, prow + kt * 32);
                ldmx4(kl4, prow + (uint32_t)(AT_LOFF * 2) + kt * 32);
                mma_f32(a0, qh[kt][0], qh[kt][1], qh[kt][2], qh[kt][3], kh4[0], kh4[1]);
                mma_f32(a0, qh[kt][0], qh[kt][1], qh[kt][2], qh[kt][3], kl4[0], kl4[1]);
                mma_f32(a0, ql[kt][0], ql[kt][1], ql[kt][2], ql[kt][3], kh4[0], kh4[1]);
                mma_f32(a1, qh[kt][0], qh[kt][1], qh[kt][2], qh[kt][3], kh4[2], kh4[3]);
                mma_f32(a1, qh[kt][0], qh[kt][1], qh[kt][2], qh[kt][3], kl4[2], kl4[3]);
                mma_f32(a1, ql[kt][0], ql[kt][1], ql[kt][2], ql[kt][3], kh4[2], kh4[3]);
            }
        }
    };

    s_chunk(AT_BUF0, 0);
    __syncthreads();
    load_kv(0, 1, AT_BUF0);        // V0 -> buf0
    cp_wait<1>();                  // K1 done
    __syncthreads();
    s_chunk(AT_BUF1, 16);
    __syncthreads();
    load_kv(128, 1, AT_BUF1);      // V1 -> buf1

    // ---- softmax ----
    const float scale = 0.125f;
    float mx0 = -1e30f, mx1 = -1e30f;
#pragma unroll
    for (int t = 0; t < 32; t++) {
        mx0 = fmaxf(mx0, fmaxf(acc[t][0], acc[t][1]));
        mx1 = fmaxf(mx1, fmaxf(acc[t][2], acc[t][3]));
    }
    mx0 = fmaxf(mx0, __shfl_xor_sync(0xffffffffu, mx0, 1));
    mx0 = fmaxf(mx0, __shfl_xor_sync(0xffffffffu, mx0, 2));
    mx1 = fmaxf(mx1, __shfl_xor_sync(0xffffffffu, mx1, 1));
    mx1 = fmaxf(mx1, __shfl_xor_sync(0xffffffffu, mx1, 2));
    float s0 = 0.f, s1 = 0.f;
#pragma unroll
    for (int t = 0; t < 32; t++) {
        acc[t][0] = __expf((acc[t][0] - mx0) * scale); s0 += acc[t][0];
        acc[t][1] = __expf((acc[t][1] - mx0) * scale); s0 += acc[t][1];
        acc[t][2] = __expf((acc[t][2] - mx1) * scale); s1 += acc[t][2];
        acc[t][3] = __expf((acc[t][3] - mx1) * scale); s1 += acc[t][3];
    }
    s0 += __shfl_xor_sync(0xffffffffu, s0, 1);
    s0 += __shfl_xor_sync(0xffffffffu, s0, 2);
    s1 += __shfl_xor_sync(0xffffffffu, s1, 1);
    s1 += __shfl_xor_sync(0xffffffffu, s1, 2);
    float i0 = 1.f / s0, i1 = 1.f / s1;
#pragma unroll
    for (int t = 0; t < 32; t++) {
        acc[t][0] *= i0; acc[t][1] *= i0; acc[t][2] *= i1; acc[t][3] *= i1;
    }

    // ---- write attn probs (fp32, streaming) ----
    {
        float* ar0 = attn + ((size_t)((b * HEADS + h) * NMM) + q0 + wid * 16 + lr) * NSRC + 2 * lc;
        float* ar1 = ar0 + (size_t)8 * NSRC;
#pragma unroll
        for (int t = 0; t < 32; t++) {
            st_cs_f2(ar0 + t * 8, acc[t][0], acc[t][1]);
            st_cs_f2(ar1 + t * 8, acc[t][2], acc[t][3]);
        }
    }

    // ---- P -> fp16 hi/lo A-fragments ----
    uint32_t ph[16][4], pl[16][4];
#pragma unroll
    for (int t = 0; t < 16; t++) {
        split2h(acc[2 * t][0],     acc[2 * t][1],     ph[t][0], pl[t][0]);
        split2h(acc[2 * t][2],     acc[2 * t][3],     ph[t][1], pl[t][1]);
        split2h(acc[2 * t + 1][0], acc[2 * t + 1][1], ph[t][2], pl[t][2]);
        split2h(acc[2 * t + 1][2], acc[2 * t + 1][3], ph[t][3], pl[t][3]);
    }

    // ---- O = P V (3-term, fp32 acc) ----
    float oacc[8][4];
#pragma unroll
    for (int nd = 0; nd < 8; nd++)
#pragma unroll
        for (int v = 0; v < 4; v++) oacc[nd][v] = 0.f;

    auto pv_chunk = [&](uint32_t bufoff, int ktb) {
        uint32_t vbase = smb + (uint32_t)(bufoff + (lane & 15) * QSTR + (lane >> 4) * 8) * 2;
#pragma unroll
        for (int ktl = 0; ktl < 8; ktl++) {
            int kt = ktb + ktl;
            uint32_t vrow = vbase + (uint32_t)(ktl * 16 * QSTR) * 2;
#pragma unroll
            for (int ndp = 0; ndp < 4; ndp++) {
                uint32_t vh4[4], vl4[4];
                ldmx4t(vh4, vrow + ndp * 32);
                ldmx4t(vl4, vrow + (uint32_t)(AT_LOFF * 2) + ndp * 32);
                mma_f32(oacc[2 * ndp],     ph[kt][0], ph[kt][1], ph[kt][2], ph[kt][3], vh4[0], vh4[1]);
                mma_f32(oacc[2 * ndp],     ph[kt][0], ph[kt][1], ph[kt][2], ph[kt][3], vl4[0], vl4[1]);
                mma_f32(oacc[2 * ndp],     pl[kt][0], pl[kt][1], pl[kt][2], pl[kt][3], vh4[0], vh4[1]);
                mma_f32(oacc[2 * ndp + 1], ph[kt][0], ph[kt][1], ph[kt][2], ph[kt][3], vh4[2], vh4[3]);
                mma_f32(oacc[2 * ndp + 1], ph[kt][0], ph[kt][1], ph[kt][2], ph[kt][3], vl4[2], vl4[3]);
                mma_f32(oacc[2 * ndp + 1], pl[kt][0], pl[kt][1], pl[kt][2], pl[kt][3], vh4[2], vh4[3]);
            }
        }
    };

    cp_wait<1>();                  // V0 arrived
    __syncthreads();
    pv_chunk(AT_BUF0, 0);
    cp_wait<0>();                  // V1 arrived
    __syncthreads();
    pv_chunk(AT_BUF1, 8);

    // ---- write O as fp16 hi/lo ----
    {
        size_t row0 = (size_t)(b * NMM + q0 + wid * 16 + lr);
        __half* oh0 = Ohi + row0 * DIM + h * HD + 2 * lc;
        __half* ol0 = Olo + row0 * DIM + h * HD + 2 * lc;
        __half* oh1 = oh0 + (size_t)8 * DIM;
        __half* ol1 = ol0 + (size_t)8 * DIM;
#pragma unroll
        for (int nd = 0; nd < 8; nd++) {
            uint32_t hh, ll;
            split2h(oacc[nd][0], oacc[nd][1], hh, ll);
            *(uint32_t*)(oh0 + nd * 8) = hh;
            *(uint32_t*)(ol0 + nd * 8) = ll;
            split2h(oacc[nd][2], oacc[nd][3], hh, ll);
            *(uint32_t*)(oh1 + nd * 8) = hh;
            *(uint32_t*)(ol1 + nd * 8) = ll;
        }
    }
}

// ---------------------------------------------------------------------------
extern "C" void kernel_launch(void* const* d_in, const int* in_sizes, int n_in,
                              void* d_out, int out_size)
{
    const float* xmm   = (const float*)d_in[0];
    const float* xv    = (const float*)d_in[1];
    const float* xa    = (const float*)d_in[2];
    const float* Wq    = (const float*)d_in[3];
    const float* Wkv   = (const float*)d_in[4];
    const float* Wproj = (const float*)d_in[5];
    const float* bproj = (const float*)d_in[6];

    float* out = (float*)d_out;

    float* attn_fb;
    cudaGetSymbolAddress((void**)&attn_fb, g_attn_fallback);

    __half *Axh, *Axl, *Ash, *Asl;
    __half *Qh, *Ql, *KVh, *KVl, *Oh, *Ol;
    __half *Wqt, *Wkt, *Wpt;
    cudaGetSymbolAddress((void**)&Axh, g_Axmm_hi);
    cudaGetSymbolAddress((void**)&Axl, g_Axmm_lo);
    cudaGetSymbolAddress((void**)&Ash, g_Asrc_hi);
    cudaGetSymbolAddress((void**)&Asl, g_Asrc_lo);
    cudaGetSymbolAddress((void**)&Qh,  g_Qh);
    cudaGetSymbolAddress((void**)&Ql,  g_Ql);
    cudaGetSymbolAddress((void**)&KVh, g_KVh);
    cudaGetSymbolAddress((void**)&KVl, g_KVl);
    cudaGetSymbolAddress((void**)&Oh,  g_Oh);
    cudaGetSymbolAddress((void**)&Ol,  g_Ol);
    cudaGetSymbolAddress((void**)&Wqt, g_Wqt);
    cudaGetSymbolAddress((void**)&Wkt, g_Wkvt);
    cudaGetSymbolAddress((void**)&Wpt, g_Wpt);

    const size_t out_elems  = (size_t)MQ * DIM;
    const size_t attn_elems = (size_t)BS * HEADS * NMM * NSRC;
    float* attn_out = ((size_t)out_size >= out_elems + attn_elems)
                        ? out + out_elems : attn_fb;

    cudaFuncSetAttribute((const void*)gemm_fp16s<true, DIM>,
                         cudaFuncAttributeMaxDynamicSharedMemorySize, GEMM_SMEM);
    cudaFuncSetAttribute((const void*)gemm_fp16s<true, 2 * DIM>,
                         cudaFuncAttributeMaxDynamicSharedMemorySize, GEMM_SMEM);
    cudaFuncSetAttribute((const void*)gemm_fp16s<false, DIM>,
                         cudaFuncAttributeMaxDynamicSharedMemorySize, GEMM_SMEM);
    cudaFuncSetAttribute(attn_mma, cudaFuncAttributeMaxDynamicSharedMemorySize, AT_SMEM_BYTES);

    // --- conversions ---
    {
        dim3 bb(32, 8);
        transpose_all<<<dim3(2 * DIM / 32, DIM / 32, 3), bb>>>(
            Wq, Wqt, Wkv, Wkt, Wproj, Wpt);
    }
    split_all_v4<<<dim3(1024, 2), 256>>>((const float4*)xmm,
                                         (const float4*)xv, (const float4*)xa,
                                         (uint2*)Axh, (uint2*)Axl,
                                         (uint2*)Ash, (uint2*)Asl);

    // --- Q = xmm @ Wq  -> fp16 hi/lo ---
    gemm_fp16s<true, DIM><<<dim3(DIM / 128, MQ / 128), 256, GEMM_SMEM>>>(
        Axh, Axl, Wqt, nullptr, Qh, Ql, nullptr);
    // --- KV = concat(xv,xa) @ Wkv -> fp16 hi/lo ---
    gemm_fp16s<true, 2 * DIM><<<dim3(2 * DIM / 128, MQ / 128), 256, GEMM_SMEM>>>(
        Ash, Asl, Wkt, nullptr, KVh, KVl, nullptr);
    // --- attention ---
    attn_mma<<<dim3(NMM / 128, HEADS, BS), 256, AT_SMEM_BYTES>>>(
        Qh, Ql, KVh, KVl, attn_out, Oh, Ol);
    // --- out = O @ Wproj + bproj (fp32) ---
    gemm_fp16s<false, DIM><<<dim3(DIM / 128, MQ / 128), 256, GEMM_SMEM>>>(
        Oh, Ol, Wpt, out, nullptr, nullptr, bproj);
}

// round 16
// speedup vs baseline: 1.7130x; 1.0802x over previous
#include <cuda_runtime.h>
#include <cuda_fp16.h>
#include <cstdint>
#include <math.h>

#define DIM   768
#define HEADS 12
#define HD    64
#define BS    32
#define NMM   256
#define NV    196
#define NA    60
#define NSRC  256            // NV + NA
#define MQ    (BS * NMM)     // 8192

// ---------------------------------------------------------------------------
// Scratch (static __device__ globals; allocation is forbidden)
// ---------------------------------------------------------------------------
__device__ float g_attn_fallback[(size_t)BS * HEADS * NMM * NSRC];

__device__ __half g_Axmm_hi[(size_t)MQ * DIM];
__device__ __half g_Axmm_lo[(size_t)MQ * DIM];
__device__ __half g_Asrc_hi[(size_t)MQ * DIM];
__device__ __half g_Asrc_lo[(size_t)MQ * DIM];
__device__ __half g_Qh [(size_t)MQ * DIM];
__device__ __half g_Ql [(size_t)MQ * DIM];
__device__ __half g_KVh[(size_t)MQ * 2 * DIM];
__device__ __half g_KVl[(size_t)MQ * 2 * DIM];
__device__ __half g_Oh [(size_t)MQ * DIM];
__device__ __half g_Ol [(size_t)MQ * DIM];
__device__ __half g_Wqt [(size_t)DIM * DIM];
__device__ __half g_Wkvt[(size_t)2 * DIM * DIM];
__device__ __half g_Wpt [(size_t)DIM * DIM];

// ---------------------------------------------------------------------------
// helpers
// ---------------------------------------------------------------------------
__device__ __forceinline__ uint32_t smem_u32(const void* p) {
    uint32_t a;
    asm("{ .reg .u64 t; cvta.to.shared.u64 t, %1; cvt.u32.u64 %0, t; }" : "=r"(a) : "l"(p));
    return a;
}
__device__ __forceinline__ uint32_t pack_h2(__half a, __half b) {
    __half2 t = __halves2half2(a, b);
    return *reinterpret_cast<uint32_t*>(&t);
}
__device__ __forceinline__ void split2h(float a, float b, uint32_t& hi, uint32_t& lo) {
    __half ha = __float2half_rn(a), hb = __float2half_rn(b);
    hi = pack_h2(ha, hb);
    lo = pack_h2(__float2half_rn(a - __half2float(ha)),
                 __float2half_rn(b - __half2float(hb)));
}
__device__ __forceinline__ void cp_async16(uint32_t saddr, const void* gptr) {
    asm volatile("cp.async.cg.shared.global [%0], [%1], 16;" :: "r"(saddr), "l"(gptr));
}
__device__ __forceinline__ void cp_commit() { asm volatile("cp.async.commit_group;"); }
template<int N_>
__device__ __forceinline__ void cp_wait() { asm volatile("cp.async.wait_group %0;" :: "n"(N_)); }

__device__ __forceinline__ void mma_f32(float* c, uint32_t a0, uint32_t a1,
                                        uint32_t a2, uint32_t a3,
                                        uint32_t b0, uint32_t b1) {
    asm volatile(
        "mma.sync.aligned.m16n8k16.row.col.f32.f16.f16.f32 "
        "{%0,%1,%2,%3}, {%4,%5,%6,%7}, {%8,%9}, {%0,%1,%2,%3};"
        : "+f"(c[0]), "+f"(c[1]), "+f"(c[2]), "+f"(c[3])
        : "r"(a0), "r"(a1), "r"(a2), "r"(a3), "r"(b0), "r"(b1));
}
__device__ __forceinline__ void ldmx4(uint32_t* r, uint32_t saddr) {
    asm volatile("ldmatrix.sync.aligned.m8n8.x4.shared.b16 {%0,%1,%2,%3}, [%4];"
                 : "=r"(r[0]), "=r"(r[1]), "=r"(r[2]), "=r"(r[3]) : "r"(saddr));
}
__device__ __forceinline__ void ldmx4t(uint32_t* r, uint32_t saddr) {
    asm volatile("ldmatrix.sync.aligned.m8n8.x4.trans.shared.b16 {%0,%1,%2,%3}, [%4];"
                 : "=r"(r[0]), "=r"(r[1]), "=r"(r[2]), "=r"(r[3]) : "r"(saddr));
}
__device__ __forceinline__ void st_cs_f2(float* p, float x, float y) {
    asm volatile("st.global.cs.v2.f32 [%0], {%1, %2};" :: "l"(p), "f"(x), "f"(y) : "memory");
}
__device__ __forceinline__ void split4h(float4 x, uint2& hi, uint2& lo) {
    uint32_t h0, l0, h1, l1;
    split2h(x.x, x.y, h0, l0);
    split2h(x.z, x.w, h1, l1);
    hi = make_uint2(h0, h1);
    lo = make_uint2(l0, l1);
}

// ---------------------------------------------------------------------------
// Merged conversion kernels: activations fp32 -> (hi, lo) fp16 split
// ---------------------------------------------------------------------------
__global__ void split_all_v4(const float4* __restrict__ xmm,
                             const float4* __restrict__ xv, const float4* __restrict__ xa,
                             uint2* __restrict__ xh, uint2* __restrict__ xl,
                             uint2* __restrict__ sh, uint2* __restrict__ sl) {
    const int D4 = DIM / 4;
    size_t n4 = (size_t)MQ * D4;
    if (blockIdx.y == 0) {
        for (size_t i = (size_t)blockIdx.x * blockDim.x + threadIdx.x; i < n4;
             i += (size_t)gridDim.x * blockDim.x) {
            uint2 H, L;
            split4h(xmm[i], H, L);
            xh[i] = H;
            xl[i] = L;
        }
    } else {
        for (size_t i = (size_t)blockIdx.x * blockDim.x + threadIdx.x; i < n4;
             i += (size_t)gridDim.x * blockDim.x) {
            size_t row = i / D4, cg = i % D4;
            int b = (int)(row >> 8), t = (int)(row & 255);
            float4 x = (t < NV) ? xv[((size_t)b * NV + t) * D4 + cg]
                                : xa[((size_t)b * NA + (t - NV)) * D4 + cg];
            uint2 H, L;
            split4h(x, H, L);
            sh[i] = H;
            sl[i] = L;
        }
    }
}

// Weights fp32 -> transposed fp16. z: 0 = Wq, 1 = Wkv, 2 = Wproj
__global__ void transpose_all(
    const float* __restrict__ Wq,  __half* __restrict__ Tq,
    const float* __restrict__ Wkv, __half* __restrict__ Tk,
    const float* __restrict__ Wp,  __half* __restrict__ Tp)
{
    __shared__ float tile[32][33];
    int z = blockIdx.z;
    int N = (z == 1) ? 2 * DIM : DIM;
    if (blockIdx.x * 32 >= N) return;
    const float* W = (z == 0) ? Wq : (z == 1) ? Wkv : Wp;
    __half* T = (z == 0) ? Tq : (z == 1) ? Tk : Tp;

    int n0 = blockIdx.x * 32, k0 = blockIdx.y * 32;
    int tx = threadIdx.x, ty = threadIdx.y;     // (32, 8)
#pragma unroll
    for (int j = 0; j < 32; j += 8)
        tile[ty + j][tx] = W[(size_t)(k0 + ty + j) * N + (n0 + tx)];
    __syncthreads();
#pragma unroll
    for (int j = 0; j < 32; j += 8) {
        float v = tile[tx][ty + j];
        T[(size_t)(n0 + ty + j) * DIM + (k0 + tx)] = __float2half_rn(v);
    }
}

// ---------------------------------------------------------------------------
// 2-product split-fp16 GEMM body: C = (Ahi + Alo) @ Wt^T ; W plain fp16.
// CTA 128x128, 8 warps 64x32, K-chunk 32, double buffer, SINGLE sync/chunk.
// smem/stage: Ahi | Alo | B = 3 tiles of 128x40 halves.
// ---------------------------------------------------------------------------
#define CK       32
#define GK       768
#define SROW     40
#define TILE_BF  (128 * SROW)
#define ST_ELEMS (3 * TILE_BF)
#define GEMM_SMEM (2 * ST_ELEMS * 2)        // 61440 bytes

template<bool SPLIT>
__device__ __forceinline__ void gemm_body(
    const __half* __restrict__ Ahi, const __half* __restrict__ Alo,
    const __half* __restrict__ B,
    float* __restrict__ C, __half* __restrict__ Chi, __half* __restrict__ Clo,
    int m0, int n0, int NN, const float* __restrict__ bias, __half* sm)
{
    const int tid  = threadIdx.x;
    const int wid  = tid >> 5;
    const int lane = tid & 31;
    const int wm   = (wid >> 2) * 64;
    const int wn   = (wid & 3) * 32;
    constexpr int NC = GK / CK;             // 24

    const int lr = lane >> 2;
    const int lc = (lane & 3) * 2;

    const int arow = (lane & 7) + ((lane >> 3) & 1) * 8;
    const int akof = (lane >> 4) * 8;
    const int brow = (lane & 7) + ((lane >> 4) << 3);
    const int bkof = ((lane >> 3) & 1) * 8;

    float acc[4][4][4];
#pragma unroll
    for (int i = 0; i < 4; i++)
#pragma unroll
        for (int j = 0; j < 4; j++)
#pragma unroll
            for (int v = 0; v < 4; v++) acc[i][j][v] = 0.f;

    uint32_t smb = smem_u32(sm);
    const uint32_t offAh = (uint32_t)(0 * TILE_BF + (wm + arow) * SROW + akof) * 2;
    const uint32_t offAl = (uint32_t)(1 * TILE_BF + (wm + arow) * SROW + akof) * 2;
    const uint32_t offB  = (uint32_t)(2 * TILE_BF + (wn + brow) * SROW + bkof) * 2;

    auto load_chunk = [&](int c, int s) {
        uint32_t base = smb + (uint32_t)s * ST_ELEMS * 2;
        int k0 = c * CK;
#pragma unroll
        for (int it = 0; it < 2; it++) {
            int e   = tid + it * 256;
            int r   = e >> 2, seg = e & 3;
            uint32_t doff = (uint32_t)(r * SROW + seg * 8) * 2;
            size_t  goffA = (size_t)(m0 + r) * GK + k0 + seg * 8;
            size_t  goffB = (size_t)(n0 + r) * GK + k0 + seg * 8;
            cp_async16(base + 0 * TILE_BF * 2 + doff, Ahi + goffA);
            cp_async16(base + 1 * TILE_BF * 2 + doff, Alo + goffA);
            cp_async16(base + 2 * TILE_BF * 2 + doff, B + goffB);
        }
        cp_commit();
    };

    load_chunk(0, 0);

#pragma unroll 2
    for (int c = 0; c < NC; c++) {
        int s = c & 1;
        cp_wait<0>();          // chunk c landed (only pending group)
        __syncthreads();       // all warps finished compute(c-1); data visible
        if (c + 1 < NC) load_chunk(c + 1, 1 - s);   // overwrites buffer of c-1: safe

        uint32_t stg = smb + (uint32_t)s * ST_ELEMS * 2;

#pragma unroll
        for (int ks = 0; ks < 2; ks++) {
            uint32_t kbb = (uint32_t)(ks * 16) * 2;
            uint32_t bh[4][2];
#pragma unroll
            for (int p = 0; p < 2; p++) {
                uint32_t t4[4];
                ldmx4(t4, stg + offB + kbb + (uint32_t)(p * 16 * SROW) * 2);
                bh[2 * p][0] = t4[0]; bh[2 * p][1] = t4[1];
                bh[2 * p + 1][0] = t4[2]; bh[2 * p + 1][1] = t4[3];
            }
#pragma unroll
            for (int mt = 0; mt < 4; mt++) {
                uint32_t ah[4], al[4];
                ldmx4(ah, stg + offAh + kbb + (uint32_t)(mt * 16 * SROW) * 2);
                ldmx4(al, stg + offAl + kbb + (uint32_t)(mt * 16 * SROW) * 2);
#pragma unroll
                for (int nt = 0; nt < 4; nt++) {
                    mma_f32(acc[mt][nt], ah[0], ah[1], ah[2], ah[3], bh[nt][0], bh[nt][1]);
                    mma_f32(acc[mt][nt], al[0], al[1], al[2], al[3], bh[nt][0], bh[nt][1]);
                }
            }
        }
    }

#pragma unroll
    for (int mt = 0; mt < 4; mt++) {
        int r0 = m0 + wm + mt * 16 + lr;
#pragma unroll
        for (int nt = 0; nt < 4; nt++) {
            int cc = n0 + wn + nt * 8 + lc;
            if (SPLIT) {
                uint32_t h0, l0, h1, l1;
                split2h(acc[mt][nt][0], acc[mt][nt][1], h0, l0);
                split2h(acc[mt][nt][2], acc[mt][nt][3], h1, l1);
                *(uint32_t*)(Chi + (size_t)r0 * NN + cc)       = h0;
                *(uint32_t*)(Clo + (size_t)r0 * NN + cc)       = l0;
                *(uint32_t*)(Chi + (size_t)(r0 + 8) * NN + cc) = h1;
                *(uint32_t*)(Clo + (size_t)(r0 + 8) * NN + cc) = l1;
            } else {
                float b0 = bias ? bias[cc]     : 0.f;
                float b1 = bias ? bias[cc + 1] : 0.f;
                float* p0 = C + (size_t)r0 * NN + cc;
                float* p1 = C + (size_t)(r0 + 8) * NN + cc;
                p0[0] = acc[mt][nt][0] + b0;
                p0[1] = acc[mt][nt][1] + b1;
                p1[0] = acc[mt][nt][2] + b0;
                p1[1] = acc[mt][nt][3] + b1;
            }
        }
    }
}

// Fused Q+KV projection: grid (6 + 12, 64). ONE body call (no code dup).
__global__ void __launch_bounds__(256, 2) gemm_qkv(
    const __half* __restrict__ Axh, const __half* __restrict__ Axl,
    const __half* __restrict__ Wq,
    __half* __restrict__ Qh, __half* __restrict__ Ql,
    const __half* __restrict__ Ash, const __half* __restrict__ Asl,
    const __half* __restrict__ Wk,
    __half* __restrict__ KVh, __half* __restrict__ KVl)
{
    extern __shared__ __align__(16) __half sm[];
    int bx = blockIdx.x, m0 = blockIdx.y * 128;
    const __half *Ahi, *Alo, *B;
    __half *Chi, *Clo;
    int n0, NN;
    if (bx < DIM / 128) {
        Ahi = Axh; Alo = Axl; B = Wq;  Chi = Qh;  Clo = Ql;
        n0 = bx * 128; NN = DIM;
    } else {
        Ahi = Ash; Alo = Asl; B = Wk;  Chi = KVh; Clo = KVl;
        n0 = (bx - DIM / 128) * 128; NN = 2 * DIM;
    }
    gemm_body<true>(Ahi, Alo, B, nullptr, Chi, Clo, m0, n0, NN, nullptr, sm);
}

__global__ void __launch_bounds__(256, 2) gemm_proj(
    const __half* __restrict__ Ahi, const __half* __restrict__ Alo,
    const __half* __restrict__ B, float* __restrict__ C,
    const float* __restrict__ bias)
{
    extern __shared__ __align__(16) __half sm[];
    gemm_body<false>(Ahi, Alo, B, C, nullptr, nullptr,
                     blockIdx.y * 128, blockIdx.x * 128, DIM, bias, sm);
}

// ---------------------------------------------------------------------------
// HMMA flash-style attention, chunked cp.async pipeline, fp16 split,
// full 3-term, fp32 accumulation. CTA = (q-tile 128, h, b), 256 thr.
// ---------------------------------------------------------------------------
#define QSTR 72
#define AT_QH   0
#define AT_QL   (128 * QSTR)
#define AT_BUF0 (2 * 128 * QSTR)
#define AT_BUF1 (AT_BUF0 + 2 * 128 * QSTR)
#define AT_LOFF (128 * QSTR)
#define AT_SMEM_ELE (AT_BUF1 + 2 * 128 * QSTR)   // 55296 halves
#define AT_SMEM_BYTES (AT_SMEM_ELE * 2)          // 110592

__global__ void __launch_bounds__(256) attn_mma(
    const __half* __restrict__ Qhi, const __half* __restrict__ Qlo,
    const __half* __restrict__ KVhi, const __half* __restrict__ KVlo,
    float* __restrict__ attn,
    __half* __restrict__ Ohi, __half* __restrict__ Olo)
{
    extern __shared__ __align__(16) __half asm_[];
    const int tid  = threadIdx.x;
    const int wid  = tid >> 5;
    const int lane = tid & 31;
    const int lr   = lane >> 2;
    const int lc   = lane & 3;
    const int b    = blockIdx.z;
    const int h    = blockIdx.y;
    const int q0   = blockIdx.x * 128;

    const int arow = (lane & 7) + ((lane >> 3) & 1) * 8;
    const int akof = (lane >> 4) * 8;
    const int brow = (lane & 7) + ((lane >> 4) << 3);
    const int bkof = ((lane >> 3) & 1) * 8;

    uint32_t smb = smem_u32(asm_);

    auto load_kv = [&](int key0, int is_v, uint32_t bufoff) {
        const __half* sh = KVhi + ((size_t)b * NSRC + key0) * (2 * DIM) + h * HD + is_v * DIM;
        const __half* sl = KVlo + ((size_t)b * NSRC + key0) * (2 * DIM) + h * HD + is_v * DIM;
#pragma unroll
        for (int it = 0; it < 4; it++) {
            int e = tid + it * 256;
            int r = e >> 3, s = e & 7;
            size_t go = (size_t)r * (2 * DIM) + s * 8;
            uint32_t doff = (uint32_t)(r * QSTR + s * 8) * 2;
            cp_async16(smb + (bufoff * 2) + doff, sh + go);
            cp_async16(smb + ((bufoff + AT_LOFF) * 2) + doff, sl + go);
        }
        cp_commit();
    };

    // ---- prologue: async K0, K1; regular Q ----
    load_kv(0,   0, AT_BUF0);
    load_kv(128, 0, AT_BUF1);
    {
        const __half* Qgh = Qhi + ((size_t)(b * NMM + q0)) * DIM + h * HD;
        const __half* Qgl = Qlo + ((size_t)(b * NMM + q0)) * DIM + h * HD;
#pragma unroll
        for (int it = 0; it < 4; it++) {
            int e = tid + it * 256;
            int r = e >> 3, s = e & 7;
            *(uint4*)&asm_[AT_QH + r * QSTR + s * 8] = *(const uint4*)(Qgh + (size_t)r * DIM + s * 8);
            *(uint4*)&asm_[AT_QL + r * QSTR + s * 8] = *(const uint4*)(Qgl + (size_t)r * DIM + s * 8);
        }
    }
    cp_wait<1>();
    __syncthreads();

    // ---- Q fragments ----
    uint32_t qh[4][4], ql[4][4];
    {
        uint32_t qoff = smb + (uint32_t)((wid * 16 + arow) * QSTR + akof) * 2;
#pragma unroll
        for (int kt = 0; kt < 4; kt++) {
            ldmx4(qh[kt], qoff + (uint32_t)(AT_QH * 2) + kt * 32);
            ldmx4(ql[kt], qoff + (uint32_t)(AT_QL * 2) + kt * 32);
        }
    }

    float acc[32][4];
#pragma unroll
    for (int t = 0; t < 32; t++)
#pragma unroll
        for (int v = 0; v < 4; v++) acc[t][v] = 0.f;

    auto s_chunk = [&](uint32_t bufoff, int accb) {
        uint32_t kb = smb + (uint32_t)(bufoff + brow * QSTR + bkof) * 2;
#pragma unroll
        for (int p = 0; p < 8; p++) {
            uint32_t prow = kb + (uint32_t)(p * 16 * QSTR) * 2;
            float* a0 = acc[accb + 2 * p];
            float* a1 = acc[accb + 2 * p + 1];
#pragma unroll
            for (int kt = 0; kt < 4; kt++) {
                uint32_t kh4[4], kl4[4];
                ldmx4(kh4, prow + kt * 32);
                ldmx4(kl4, prow + (uint32_t)(AT_LOFF * 2) + kt * 32);
                mma_f32(a0, qh[kt][0], qh[kt][1], qh[kt][2], qh[kt][3], kh4[0], kh4[1]);
                mma_f32(a0, qh[kt][0], qh[kt][1], qh[kt][2], qh[kt][3], kl4[0], kl4[1]);
                mma_f32(a0, ql[kt][0], ql[kt][1], ql[kt][2], ql[kt][3], kh4[0], kh4[1]);
                mma_f32(a1, qh[kt][0], qh[kt][1], qh[kt][2], qh[kt][3], kh4[2], kh4[3]);
                mma_f32(a1, qh[kt][0], qh[kt][1], qh[kt][2], qh[kt][3], kl4[2], kl4[3]);
                mma_f32(a1, ql[kt][0], ql[kt][1], ql[kt][2], ql[kt][3], kh4[2], kh4[3]);
            }
        }
    };

    s_chunk(AT_BUF0, 0);
    __syncthreads();
    load_kv(0, 1, AT_BUF0);        // V0 -> buf0
    cp_wait<1>();                  // K1 done
    __syncthreads();
    s_chunk(AT_BUF1, 16);
    __syncthreads();
    load_kv(128, 1, AT_BUF1);      // V1 -> buf1

    // ---- softmax ----
    const float scale = 0.125f;
    float mx0 = -1e30f, mx1 = -1e30f;
#pragma unroll
    for (int t = 0; t < 32; t++) {
        mx0 = fmaxf(mx0, fmaxf(acc[t][0], acc[t][1]));
        mx1 = fmaxf(mx1, fmaxf(acc[t][2], acc[t][3]));
    }
    mx0 = fmaxf(mx0, __shfl_xor_sync(0xffffffffu, mx0, 1));
    mx0 = fmaxf(mx0, __shfl_xor_sync(0xffffffffu, mx0, 2));
    mx1 = fmaxf(mx1, __shfl_xor_sync(0xffffffffu, mx1, 1));
    mx1 = fmaxf(mx1, __shfl_xor_sync(0xffffffffu, mx1, 2));
    float s0 = 0.f, s1 = 0.f;
#pragma unroll
    for (int t = 0; t < 32; t++) {
        acc[t][0] = __expf((acc[t][0] - mx0) * scale); s0 += acc[t][0];
        acc[t][1] = __expf((acc[t][1] - mx0) * scale); s0 += acc[t][1];
        acc[t][2] = __expf((acc[t][2] - mx1) * scale); s1 += acc[t][2];
        acc[t][3] = __expf((acc[t][3] - mx1) * scale); s1 += acc[t][3];
    }
    s0 += __shfl_xor_sync(0xffffffffu, s0, 1);
    s0 += __shfl_xor_sync(0xffffffffu, s0, 2);
    s1 += __shfl_xor_sync(0xffffffffu, s1, 1);
    s1 += __shfl_xor_sync(0xffffffffu, s1, 2);
    float i0 = 1.f / s0, i1 = 1.f / s1;
#pragma unroll
    for (int t = 0; t < 32; t++) {
        acc[t][0] *= i0; acc[t][1] *= i0; acc[t][2] *= i1; acc[t][3] *= i1;
    }

    // ---- write attn probs (fp32, streaming) ----
    {
        float* ar0 = attn + ((size_t)((b * HEADS + h) * NMM) + q0 + wid * 16 + lr) * NSRC + 2 * lc;
        float* ar1 = ar0 + (size_t)8 * NSRC;
#pragma unroll
        for (int t = 0; t < 32; t++) {
            st_cs_f2(ar0 + t * 8, acc[t][0], acc[t][1]);
            st_cs_f2(ar1 + t * 8, acc[t][2], acc[t][3]);
        }
    }

    // ---- P -> fp16 hi/lo A-fragments ----
    uint32_t ph[16][4], pl[16][4];
#pragma unroll
    for (int t = 0; t < 16; t++) {
        split2h(acc[2 * t][0],     acc[2 * t][1],     ph[t][0], pl[t][0]);
        split2h(acc[2 * t][2],     acc[2 * t][3],     ph[t][1], pl[t][1]);
        split2h(acc[2 * t + 1][0], acc[2 * t + 1][1], ph[t][2], pl[t][2]);
        split2h(acc[2 * t + 1][2], acc[2 * t + 1][3], ph[t][3], pl[t][3]);
    }

    // ---- O = P V (3-term, fp32 acc) ----
    float oacc[8][4];
#pragma unroll
    for (int nd = 0; nd < 8; nd++)
#pragma unroll
        for (int v = 0; v < 4; v++) oacc[nd][v] = 0.f;

    auto pv_chunk = [&](uint32_t bufoff, int ktb) {
        uint32_t vbase = smb + (uint32_t)(bufoff + (lane & 15) * QSTR + (lane >> 4) * 8) * 2;
#pragma unroll
        for (int ktl = 0; ktl < 8; ktl++) {
            int kt = ktb + ktl;
            uint32_t vrow = vbase + (uint32_t)(ktl * 16 * QSTR) * 2;
#pragma unroll
            for (int ndp = 0; ndp < 4; ndp++) {
                uint32_t vh4[4], vl4[4];
                ldmx4t(vh4, vrow + ndp * 32);
                ldmx4t(vl4, vrow + (uint32_t)(AT_LOFF * 2) + ndp * 32);
                mma_f32(oacc[2 * ndp],     ph[kt][0], ph[kt][1], ph[kt][2], ph[kt][3], vh4[0], vh4[1]);
                mma_f32(oacc[2 * ndp],     ph[kt][0], ph[kt][1], ph[kt][2], ph[kt][3], vl4[0], vl4[1]);
                mma_f32(oacc[2 * ndp],     pl[kt][0], pl[kt][1], pl[kt][2], pl[kt][3], vh4[0], vh4[1]);
                mma_f32(oacc[2 * ndp + 1], ph[kt][0], ph[kt][1], ph[kt][2], ph[kt][3], vh4[2], vh4[3]);
                mma_f32(oacc[2 * ndp + 1], ph[kt][0], ph[kt][1], ph[kt][2], ph[kt][3], vl4[2], vl4[3]);
                mma_f32(oacc[2 * ndp + 1], pl[kt][0], pl[kt][1], pl[kt][2], pl[kt][3], vh4[2], vh4[3]);
            }
        }
    };

    cp_wait<1>();                  // V0 arrived
    __syncthreads();
    pv_chunk(AT_BUF0, 0);
    cp_wait<0>();                  // V1 arrived
    __syncthreads();
    pv_chunk(AT_BUF1, 8);

    // ---- write O as fp16 hi/lo ----
    {
        size_t row0 = (size_t)(b * NMM + q0 + wid * 16 + lr);
        __half* oh0 = Ohi + row0 * DIM + h * HD + 2 * lc;
        __half* ol0 = Olo + row0 * DIM + h * HD + 2 * lc;
        __half* oh1 = oh0 + (size_t)8 * DIM;
        __half* ol1 = ol0 + (size_t)8 * DIM;
#pragma unroll
        for (int nd = 0; nd < 8; nd++) {
            uint32_t hh, ll;
            split2h(oacc[nd][0], oacc[nd][1], hh, ll);
            *(uint32_t*)(oh0 + nd * 8) = hh;
            *(uint32_t*)(ol0 + nd * 8) = ll;
            split2h(oacc[nd][2], oacc[nd][3], hh, ll);
            *(uint32_t*)(oh1 + nd * 8) = hh;
            *(uint32_t*)(ol1 + nd * 8) = ll;
        }
    }
}

// ---------------------------------------------------------------------------
extern "C" void kernel_launch(void* const* d_in, const int* in_sizes, int n_in,
                              void* d_out, int out_size)
{
    const float* xmm   = (const float*)d_in[0];
    const float* xv    = (const float*)d_in[1];
    const float* xa    = (const float*)d_in[2];
    const float* Wq    = (const float*)d_in[3];
    const float* Wkv   = (const float*)d_in[4];
    const float* Wproj = (const float*)d_in[5];
    const float* bproj = (const float*)d_in[6];

    float* out = (float*)d_out;

    float* attn_fb;
    cudaGetSymbolAddress((void**)&attn_fb, g_attn_fallback);

    __half *Axh, *Axl, *Ash, *Asl;
    __half *Qh, *Ql, *KVh, *KVl, *Oh, *Ol;
    __half *Wqt, *Wkt, *Wpt;
    cudaGetSymbolAddress((void**)&Axh, g_Axmm_hi);
    cudaGetSymbolAddress((void**)&Axl, g_Axmm_lo);
    cudaGetSymbolAddress((void**)&Ash, g_Asrc_hi);
    cudaGetSymbolAddress((void**)&Asl, g_Asrc_lo);
    cudaGetSymbolAddress((void**)&Qh,  g_Qh);
    cudaGetSymbolAddress((void**)&Ql,  g_Ql);
    cudaGetSymbolAddress((void**)&KVh, g_KVh);
    cudaGetSymbolAddress((void**)&KVl, g_KVl);
    cudaGetSymbolAddress((void**)&Oh,  g_Oh);
    cudaGetSymbolAddress((void**)&Ol,  g_Ol);
    cudaGetSymbolAddress((void**)&Wqt, g_Wqt);
    cudaGetSymbolAddress((void**)&Wkt, g_Wkvt);
    cudaGetSymbolAddress((void**)&Wpt, g_Wpt);

    const size_t out_elems  = (size_t)MQ * DIM;
    const size_t attn_elems = (size_t)BS * HEADS * NMM * NSRC;
    float* attn_out = ((size_t)out_size >= out_elems + attn_elems)
                        ? out + out_elems : attn_fb;

    cudaFuncSetAttribute(gemm_qkv,  cudaFuncAttributeMaxDynamicSharedMemorySize, GEMM_SMEM);
    cudaFuncSetAttribute(gemm_proj, cudaFuncAttributeMaxDynamicSharedMemorySize, GEMM_SMEM);
    cudaFuncSetAttribute(attn_mma,  cudaFuncAttributeMaxDynamicSharedMemorySize, AT_SMEM_BYTES);

    // --- conversions ---
    {
        dim3 bb(32, 8);
        transpose_all<<<dim3(2 * DIM / 32, DIM / 32, 3), bb>>>(
            Wq, Wqt, Wkv, Wkt, Wproj, Wpt);
    }
    split_all_v4<<<dim3(1024, 2), 256>>>((const float4*)xmm,
                                         (const float4*)xv, (const float4*)xa,
                                         (uint2*)Axh, (uint2*)Axl,
                                         (uint2*)Ash, (uint2*)Asl);

    // --- fused Q + KV projection (one launch, one tail) ---
    gemm_qkv<<<dim3(3 * DIM / 128, MQ / 128), 256, GEMM_SMEM>>>(
        Axh, Axl, Wqt, Qh, Ql,
        Ash, Asl, Wkt, KVh, KVl);
    // --- attention ---
    attn_mma<<<dim3(NMM / 128, HEADS, BS), 256, AT_SMEM_BYTES>>>(
        Qh, Ql, KVh, KVl, attn_out, Oh, Ol);
    // --- out = O @ Wproj + bproj (fp32) ---
    gemm_proj<<<dim3(DIM / 128, MQ / 128), 256, GEMM_SMEM>>>(
        Oh, Ol, Wpt, out, bproj);
}

// round 17
// speedup vs baseline: 1.7578x; 1.0262x over previous
#include <cuda_runtime.h>
#include <cuda_fp16.h>
#include <cstdint>
#include <math.h>

#define DIM   768
#define HEADS 12
#define HD    64
#define BS    32
#define NMM   256
#define NV    196
#define NA    60
#define NSRC  256            // NV + NA
#define MQ    (BS * NMM)     // 8192

// ---------------------------------------------------------------------------
// Scratch (static __device__ globals; allocation is forbidden)
// ---------------------------------------------------------------------------
__device__ float g_attn_fallback[(size_t)BS * HEADS * NMM * NSRC];

__device__ __half g_Axmm_hi[(size_t)MQ * DIM];
__device__ __half g_Axmm_lo[(size_t)MQ * DIM];
__device__ __half g_Asrc_hi[(size_t)MQ * DIM];
__device__ __half g_Asrc_lo[(size_t)MQ * DIM];
__device__ __half g_Qh [(size_t)MQ * DIM];
__device__ __half g_Ql [(size_t)MQ * DIM];
__device__ __half g_KVh[(size_t)MQ * 2 * DIM];
__device__ __half g_KVl[(size_t)MQ * 2 * DIM];
__device__ __half g_Oh [(size_t)MQ * DIM];
__device__ __half g_Ol [(size_t)MQ * DIM];
__device__ __half g_Wqt [(size_t)DIM * DIM];
__device__ __half g_Wkvt[(size_t)2 * DIM * DIM];
__device__ __half g_Wpt [(size_t)DIM * DIM];

// ---------------------------------------------------------------------------
// helpers
// ---------------------------------------------------------------------------
__device__ __forceinline__ uint32_t smem_u32(const void* p) {
    uint32_t a;
    asm("{ .reg .u64 t; cvta.to.shared.u64 t, %1; cvt.u32.u64 %0, t; }" : "=r"(a) : "l"(p));
    return a;
}
__device__ __forceinline__ uint32_t pack_h2(__half a, __half b) {
    __half2 t = __halves2half2(a, b);
    return *reinterpret_cast<uint32_t*>(&t);
}
__device__ __forceinline__ void split2h(float a, float b, uint32_t& hi, uint32_t& lo) {
    __half ha = __float2half_rn(a), hb = __float2half_rn(b);
    hi = pack_h2(ha, hb);
    lo = pack_h2(__float2half_rn(a - __half2float(ha)),
                 __float2half_rn(b - __half2float(hb)));
}
__device__ __forceinline__ void cp_async16(uint32_t saddr, const void* gptr) {
    asm volatile("cp.async.cg.shared.global [%0], [%1], 16;" :: "r"(saddr), "l"(gptr));
}
__device__ __forceinline__ void cp_commit() { asm volatile("cp.async.commit_group;"); }
template<int N_>
__device__ __forceinline__ void cp_wait() { asm volatile("cp.async.wait_group %0;" :: "n"(N_)); }

__device__ __forceinline__ void mma_f32(float* c, uint32_t a0, uint32_t a1,
                                        uint32_t a2, uint32_t a3,
                                        uint32_t b0, uint32_t b1) {
    asm volatile(
        "mma.sync.aligned.m16n8k16.row.col.f32.f16.f16.f32 "
        "{%0,%1,%2,%3}, {%4,%5,%6,%7}, {%8,%9}, {%0,%1,%2,%3};"
        : "+f"(c[0]), "+f"(c[1]), "+f"(c[2]), "+f"(c[3])
        : "r"(a0), "r"(a1), "r"(a2), "r"(a3), "r"(b0), "r"(b1));
}
__device__ __forceinline__ void ldmx4(uint32_t* r, uint32_t saddr) {
    asm volatile("ldmatrix.sync.aligned.m8n8.x4.shared.b16 {%0,%1,%2,%3}, [%4];"
                 : "=r"(r[0]), "=r"(r[1]), "=r"(r[2]), "=r"(r[3]) : "r"(saddr));
}
__device__ __forceinline__ void ldmx4t(uint32_t* r, uint32_t saddr) {
    asm volatile("ldmatrix.sync.aligned.m8n8.x4.trans.shared.b16 {%0,%1,%2,%3}, [%4];"
                 : "=r"(r[0]), "=r"(r[1]), "=r"(r[2]), "=r"(r[3]) : "r"(saddr));
}
__device__ __forceinline__ void st_cs_f2(float* p, float x, float y) {
    asm volatile("st.global.cs.v2.f32 [%0], {%1, %2};" :: "l"(p), "f"(x), "f"(y) : "memory");
}
__device__ __forceinline__ void split4h(float4 x, uint2& hi, uint2& lo) {
    uint32_t h0, l0, h1, l1;
    split2h(x.x, x.y, h0, l0);
    split2h(x.z, x.w, h1, l1);
    hi = make_uint2(h0, h1);
    lo = make_uint2(l0, l1);
}

// ---------------------------------------------------------------------------
// Merged conversion kernels: activations fp32 -> (hi, lo) fp16 split
// ---------------------------------------------------------------------------
__global__ void split_all_v4(const float4* __restrict__ xmm,
                             const float4* __restrict__ xv, const float4* __restrict__ xa,
                             uint2* __restrict__ xh, uint2* __restrict__ xl,
                             uint2* __restrict__ sh, uint2* __restrict__ sl) {
    const int D4 = DIM / 4;
    size_t n4 = (size_t)MQ * D4;
    if (blockIdx.y == 0) {
        for (size_t i = (size_t)blockIdx.x * blockDim.x + threadIdx.x; i < n4;
             i += (size_t)gridDim.x * blockDim.x) {
            uint2 H, L;
            split4h(xmm[i], H, L);
            xh[i] = H;
            xl[i] = L;
        }
    } else {
        for (size_t i = (size_t)blockIdx.x * blockDim.x + threadIdx.x; i < n4;
             i += (size_t)gridDim.x * blockDim.x) {
            size_t row = i / D4, cg = i % D4;
            int b = (int)(row >> 8), t = (int)(row & 255);
            float4 x = (t < NV) ? xv[((size_t)b * NV + t) * D4 + cg]
                                : xa[((size_t)b * NA + (t - NV)) * D4 + cg];
            uint2 H, L;
            split4h(x, H, L);
            sh[i] = H;
            sl[i] = L;
        }
    }
}

// Weights fp32 -> transposed fp16. z: 0 = Wq, 1 = Wkv, 2 = Wproj
__global__ void transpose_all(
    const float* __restrict__ Wq,  __half* __restrict__ Tq,
    const float* __restrict__ Wkv, __half* __restrict__ Tk,
    const float* __restrict__ Wp,  __half* __restrict__ Tp)
{
    __shared__ float tile[32][33];
    int z = blockIdx.z;
    int N = (z == 1) ? 2 * DIM : DIM;
    if (blockIdx.x * 32 >= N) return;
    const float* W = (z == 0) ? Wq : (z == 1) ? Wkv : Wp;
    __half* T = (z == 0) ? Tq : (z == 1) ? Tk : Tp;

    int n0 = blockIdx.x * 32, k0 = blockIdx.y * 32;
    int tx = threadIdx.x, ty = threadIdx.y;     // (32, 8)
#pragma unroll
    for (int j = 0; j < 32; j += 8)
        tile[ty + j][tx] = W[(size_t)(k0 + ty + j) * N + (n0 + tx)];
    __syncthreads();
#pragma unroll
    for (int j = 0; j < 32; j += 8) {
        float v = tile[tx][ty + j];
        T[(size_t)(n0 + ty + j) * DIM + (k0 + tx)] = __float2half_rn(v);
    }
}

// ---------------------------------------------------------------------------
// 2-product split-fp16 GEMM body: C = (Ahi + Alo) @ Wt^T ; W plain fp16.
// CTA 128x128, 8 warps 64x32, K-chunk 32, double buffer, single sync/chunk.
// ---------------------------------------------------------------------------
#define CK       32
#define GK       768
#define SROW     40
#define TILE_BF  (128 * SROW)
#define ST_ELEMS (3 * TILE_BF)
#define GEMM_SMEM (2 * ST_ELEMS * 2)        // 61440 bytes

template<bool SPLIT>
__device__ __forceinline__ void gemm_body(
    const __half* __restrict__ Ahi, const __half* __restrict__ Alo,
    const __half* __restrict__ B,
    float* __restrict__ C, __half* __restrict__ Chi, __half* __restrict__ Clo,
    int m0, int n0, int NN, const float* __restrict__ bias, __half* sm)
{
    const int tid  = threadIdx.x;
    const int wid  = tid >> 5;
    const int lane = tid & 31;
    const int wm   = (wid >> 2) * 64;
    const int wn   = (wid & 3) * 32;
    constexpr int NC = GK / CK;             // 24

    const int lr = lane >> 2;
    const int lc = (lane & 3) * 2;

    const int arow = (lane & 7) + ((lane >> 3) & 1) * 8;
    const int akof = (lane >> 4) * 8;
    const int brow = (lane & 7) + ((lane >> 4) << 3);
    const int bkof = ((lane >> 3) & 1) * 8;

    float acc[4][4][4];
#pragma unroll
    for (int i = 0; i < 4; i++)
#pragma unroll
        for (int j = 0; j < 4; j++)
#pragma unroll
            for (int v = 0; v < 4; v++) acc[i][j][v] = 0.f;

    uint32_t smb = smem_u32(sm);
    const uint32_t offAh = (uint32_t)(0 * TILE_BF + (wm + arow) * SROW + akof) * 2;
    const uint32_t offAl = (uint32_t)(1 * TILE_BF + (wm + arow) * SROW + akof) * 2;
    const uint32_t offB  = (uint32_t)(2 * TILE_BF + (wn + brow) * SROW + bkof) * 2;

    auto load_chunk = [&](int c, int s) {
        uint32_t base = smb + (uint32_t)s * ST_ELEMS * 2;
        int k0 = c * CK;
#pragma unroll
        for (int it = 0; it < 2; it++) {
            int e   = tid + it * 256;
            int r   = e >> 2, seg = e & 3;
            uint32_t doff = (uint32_t)(r * SROW + seg * 8) * 2;
            size_t  goffA = (size_t)(m0 + r) * GK + k0 + seg * 8;
            size_t  goffB = (size_t)(n0 + r) * GK + k0 + seg * 8;
            cp_async16(base + 0 * TILE_BF * 2 + doff, Ahi + goffA);
            cp_async16(base + 1 * TILE_BF * 2 + doff, Alo + goffA);
            cp_async16(base + 2 * TILE_BF * 2 + doff, B + goffB);
        }
        cp_commit();
    };

    load_chunk(0, 0);

#pragma unroll 2
    for (int c = 0; c < NC; c++) {
        int s = c & 1;
        cp_wait<0>();
        __syncthreads();
        if (c + 1 < NC) load_chunk(c + 1, 1 - s);

        uint32_t stg = smb + (uint32_t)s * ST_ELEMS * 2;

#pragma unroll
        for (int ks = 0; ks < 2; ks++) {
            uint32_t kbb = (uint32_t)(ks * 16) * 2;
            uint32_t bh[4][2];
#pragma unroll
            for (int p = 0; p < 2; p++) {
                uint32_t t4[4];
                ldmx4(t4, stg + offB + kbb + (uint32_t)(p * 16 * SROW) * 2);
                bh[2 * p][0] = t4[0]; bh[2 * p][1] = t4[1];
                bh[2 * p + 1][0] = t4[2]; bh[2 * p + 1][1] = t4[3];
            }
#pragma unroll
            for (int mt = 0; mt < 4; mt++) {
                uint32_t ah[4], al[4];
                ldmx4(ah, stg + offAh + kbb + (uint32_t)(mt * 16 * SROW) * 2);
                ldmx4(al, stg + offAl + kbb + (uint32_t)(mt * 16 * SROW) * 2);
#pragma unroll
                for (int nt = 0; nt < 4; nt++) {
                    mma_f32(acc[mt][nt], ah[0], ah[1], ah[2], ah[3], bh[nt][0], bh[nt][1]);
                    mma_f32(acc[mt][nt], al[0], al[1], al[2], al[3], bh[nt][0], bh[nt][1]);
                }
            }
        }
    }

#pragma unroll
    for (int mt = 0; mt < 4; mt++) {
        int r0 = m0 + wm + mt * 16 + lr;
#pragma unroll
        for (int nt = 0; nt < 4; nt++) {
            int cc = n0 + wn + nt * 8 + lc;
            if (SPLIT) {
                uint32_t h0, l0, h1, l1;
                split2h(acc[mt][nt][0], acc[mt][nt][1], h0, l0);
                split2h(acc[mt][nt][2], acc[mt][nt][3], h1, l1);
                *(uint32_t*)(Chi + (size_t)r0 * NN + cc)       = h0;
                *(uint32_t*)(Clo + (size_t)r0 * NN + cc)       = l0;
                *(uint32_t*)(Chi + (size_t)(r0 + 8) * NN + cc) = h1;
                *(uint32_t*)(Clo + (size_t)(r0 + 8) * NN + cc) = l1;
            } else {
                float b0 = bias ? bias[cc]     : 0.f;
                float b1 = bias ? bias[cc + 1] : 0.f;
                float* p0 = C + (size_t)r0 * NN + cc;
                float* p1 = C + (size_t)(r0 + 8) * NN + cc;
                p0[0] = acc[mt][nt][0] + b0;
                p0[1] = acc[mt][nt][1] + b1;
                p1[0] = acc[mt][nt][2] + b0;
                p1[1] = acc[mt][nt][3] + b1;
            }
        }
    }
}

// Fused Q+KV projection: grid (6 + 12, 64). ONE body call.
__global__ void __launch_bounds__(256, 2) gemm_qkv(
    const __half* __restrict__ Axh, const __half* __restrict__ Axl,
    const __half* __restrict__ Wq,
    __half* __restrict__ Qh, __half* __restrict__ Ql,
    const __half* __restrict__ Ash, const __half* __restrict__ Asl,
    const __half* __restrict__ Wk,
    __half* __restrict__ KVh, __half* __restrict__ KVl)
{
    extern __shared__ __align__(16) __half sm[];
    int bx = blockIdx.x, m0 = blockIdx.y * 128;
    const __half *Ahi, *Alo, *B;
    __half *Chi, *Clo;
    int n0, NN;
    if (bx < DIM / 128) {
        Ahi = Axh; Alo = Axl; B = Wq;  Chi = Qh;  Clo = Ql;
        n0 = bx * 128; NN = DIM;
    } else {
        Ahi = Ash; Alo = Asl; B = Wk;  Chi = KVh; Clo = KVl;
        n0 = (bx - DIM / 128) * 128; NN = 2 * DIM;
    }
    gemm_body<true>(Ahi, Alo, B, nullptr, Chi, Clo, m0, n0, NN, nullptr, sm);
}

__global__ void __launch_bounds__(256, 2) gemm_proj(
    const __half* __restrict__ Ahi, const __half* __restrict__ Alo,
    const __half* __restrict__ B, float* __restrict__ C,
    const float* __restrict__ bias)
{
    extern __shared__ __align__(16) __half sm[];
    gemm_body<false>(Ahi, Alo, B, C, nullptr, nullptr,
                     blockIdx.y * 128, blockIdx.x * 128, DIM, bias, sm);
}

// ---------------------------------------------------------------------------
// HMMA flash-style attention, chunked cp.async pipeline, fp16 split.
// S = 3-term (Q hi/lo x K hi/lo). PV = 2-term: (Phi+Plo) x Vhi ONLY
// (V-lo dropped: 2^-11 relative error on O, attn probs untouched).
// CTA = (q-tile 128, h, b), 256 thr.
// ---------------------------------------------------------------------------
#define QSTR 72
#define AT_QH   0
#define AT_QL   (128 * QSTR)
#define AT_BUF0 (2 * 128 * QSTR)
#define AT_BUF1 (AT_BUF0 + 2 * 128 * QSTR)
#define AT_LOFF (128 * QSTR)
#define AT_SMEM_ELE (AT_BUF1 + 2 * 128 * QSTR)   // 55296 halves
#define AT_SMEM_BYTES (AT_SMEM_ELE * 2)          // 110592

__global__ void __launch_bounds__(256) attn_mma(
    const __half* __restrict__ Qhi, const __half* __restrict__ Qlo,
    const __half* __restrict__ KVhi, const __half* __restrict__ KVlo,
    float* __restrict__ attn,
    __half* __restrict__ Ohi, __half* __restrict__ Olo)
{
    extern __shared__ __align__(16) __half asm_[];
    const int tid  = threadIdx.x;
    const int wid  = tid >> 5;
    const int lane = tid & 31;
    const int lr   = lane >> 2;
    const int lc   = lane & 3;
    const int b    = blockIdx.z;
    const int h    = blockIdx.y;
    const int q0   = blockIdx.x * 128;

    const int arow = (lane & 7) + ((lane >> 3) & 1) * 8;
    const int akof = (lane >> 4) * 8;
    const int brow = (lane & 7) + ((lane >> 4) << 3);
    const int bkof = ((lane >> 3) & 1) * 8;

    uint32_t smb = smem_u32(asm_);

    // K chunk: hi + lo ; V chunk: hi only
    auto load_k = [&](int key0, uint32_t bufoff) {
        const __half* sh = KVhi + ((size_t)b * NSRC + key0) * (2 * DIM) + h * HD;
        const __half* sl = KVlo + ((size_t)b * NSRC + key0) * (2 * DIM) + h * HD;
#pragma unroll
        for (int it = 0; it < 4; it++) {
            int e = tid + it * 256;
            int r = e >> 3, s = e & 7;
            size_t go = (size_t)r * (2 * DIM) + s * 8;
            uint32_t doff = (uint32_t)(r * QSTR + s * 8) * 2;
            cp_async16(smb + (bufoff * 2) + doff, sh + go);
            cp_async16(smb + ((bufoff + AT_LOFF) * 2) + doff, sl + go);
        }
        cp_commit();
    };
    auto load_v = [&](int key0, uint32_t bufoff) {
        const __half* sh = KVhi + ((size_t)b * NSRC + key0) * (2 * DIM) + h * HD + DIM;
#pragma unroll
        for (int it = 0; it < 4; it++) {
            int e = tid + it * 256;
            int r = e >> 3, s = e & 7;
            size_t go = (size_t)r * (2 * DIM) + s * 8;
            uint32_t doff = (uint32_t)(r * QSTR + s * 8) * 2;
            cp_async16(smb + (bufoff * 2) + doff, sh + go);
        }
        cp_commit();
    };

    // ---- prologue: async K0, K1; regular Q ----
    load_k(0,   AT_BUF0);
    load_k(128, AT_BUF1);
    {
        const __half* Qgh = Qhi + ((size_t)(b * NMM + q0)) * DIM + h * HD;
        const __half* Qgl = Qlo + ((size_t)(b * NMM + q0)) * DIM + h * HD;
#pragma unroll
        for (int it = 0; it < 4; it++) {
            int e = tid + it * 256;
            int r = e >> 3, s = e & 7;
            *(uint4*)&asm_[AT_QH + r * QSTR + s * 8] = *(const uint4*)(Qgh + (size_t)r * DIM + s * 8);
            *(uint4*)&asm_[AT_QL + r * QSTR + s * 8] = *(const uint4*)(Qgl + (size_t)r * DIM + s * 8);
        }
    }
    cp_wait<1>();
    __syncthreads();

    // ---- Q fragments ----
    uint32_t qh[4][4], ql[4][4];
    {
        uint32_t qoff = smb + (uint32_t)((wid * 16 + arow) * QSTR + akof) * 2;
#pragma unroll
        for (int kt = 0; kt < 4; kt++) {
            ldmx4(qh[kt], qoff + (uint32_t)(AT_QH * 2) + kt * 32);
            ldmx4(ql[kt], qoff + (uint32_t)(AT_QL * 2) + kt * 32);
        }
    }

    float acc[32][4];
#pragma unroll
    for (int t = 0; t < 32; t++)
#pragma unroll
        for (int v = 0; v < 4; v++) acc[t][v] = 0.f;

    auto s_chunk = [&](uint32_t bufoff, int accb) {
        uint32_t kb = smb + (uint32_t)(bufoff + brow * QSTR + bkof) * 2;
#pragma unroll
        for (int p = 0; p < 8; p++) {
            uint32_t prow = kb + (uint32_t)(p * 16 * QSTR) * 2;
            float* a0 = acc[accb + 2 * p];
            float* a1 = acc[accb + 2 * p + 1];
#pragma unroll
            for (int kt = 0; kt < 4; kt++) {
                uint32_t kh4[4], kl4[4];
                ldmx4(kh4, prow + kt * 32);
                ldmx4(kl4, prow + (uint32_t)(AT_LOFF * 2) + kt * 32);
                mma_f32(a0, qh[kt][0], qh[kt][1], qh[kt][2], qh[kt][3], kh4[0], kh4[1]);
                mma_f32(a0, qh[kt][0], qh[kt][1], qh[kt][2], qh[kt][3], kl4[0], kl4[1]);
                mma_f32(a0, ql[kt][0], ql[kt][1], ql[kt][2], ql[kt][3], kh4[0], kh4[1]);
                mma_f32(a1, qh[kt][0], qh[kt][1], qh[kt][2], qh[kt][3], kh4[2], kh4[3]);
                mma_f32(a1, qh[kt][0], qh[kt][1], qh[kt][2], qh[kt][3], kl4[2], kl4[3]);
                mma_f32(a1, ql[kt][0], ql[kt][1], ql[kt][2], ql[kt][3], kh4[2], kh4[3]);
            }
        }
    };

    s_chunk(AT_BUF0, 0);
    __syncthreads();
    load_v(0, AT_BUF0);            // V0 (hi only) -> buf0
    cp_wait<1>();                  // K1 done
    __syncthreads();
    s_chunk(AT_BUF1, 16);
    __syncthreads();
    load_v(128, AT_BUF1);          // V1 (hi only) -> buf1

    // ---- softmax ----
    const float scale = 0.125f;
    float mx0 = -1e30f, mx1 = -1e30f;
#pragma unroll
    for (int t = 0; t < 32; t++) {
        mx0 = fmaxf(mx0, fmaxf(acc[t][0], acc[t][1]));
        mx1 = fmaxf(mx1, fmaxf(acc[t][2], acc[t][3]));
    }
    mx0 = fmaxf(mx0, __shfl_xor_sync(0xffffffffu, mx0, 1));
    mx0 = fmaxf(mx0, __shfl_xor_sync(0xffffffffu, mx0, 2));
    mx1 = fmaxf(mx1, __shfl_xor_sync(0xffffffffu, mx1, 1));
    mx1 = fmaxf(mx1, __shfl_xor_sync(0xffffffffu, mx1, 2));
    float s0 = 0.f, s1 = 0.f;
#pragma unroll
    for (int t = 0; t < 32; t++) {
        acc[t][0] = __expf((acc[t][0] - mx0) * scale); s0 += acc[t][0];
        acc[t][1] = __expf((acc[t][1] - mx0) * scale); s0 += acc[t][1];
        acc[t][2] = __expf((acc[t][2] - mx1) * scale); s1 += acc[t][2];
        acc[t][3] = __expf((acc[t][3] - mx1) * scale); s1 += acc[t][3];
    }
    s0 += __shfl_xor_sync(0xffffffffu, s0, 1);
    s0 += __shfl_xor_sync(0xffffffffu, s0, 2);
    s1 += __shfl_xor_sync(0xffffffffu, s1, 1);
    s1 += __shfl_xor_sync(0xffffffffu, s1, 2);
    float i0 = 1.f / s0, i1 = 1.f / s1;
#pragma unroll
    for (int t = 0; t < 32; t++) {
        acc[t][0] *= i0; acc[t][1] *= i0; acc[t][2] *= i1; acc[t][3] *= i1;
    }

    // ---- write attn probs (fp32, streaming) ----
    {
        float* ar0 = attn + ((size_t)((b * HEADS + h) * NMM) + q0 + wid * 16 + lr) * NSRC + 2 * lc;
        float* ar1 = ar0 + (size_t)8 * NSRC;
#pragma unroll
        for (int t = 0; t < 32; t++) {
            st_cs_f2(ar0 + t * 8, acc[t][0], acc[t][1]);
            st_cs_f2(ar1 + t * 8, acc[t][2], acc[t][3]);
        }
    }

    // ---- P -> fp16 hi/lo A-fragments ----
    uint32_t ph[16][4], pl[16][4];
#pragma unroll
    for (int t = 0; t < 16; t++) {
        split2h(acc[2 * t][0],     acc[2 * t][1],     ph[t][0], pl[t][0]);
        split2h(acc[2 * t][2],     acc[2 * t][3],     ph[t][1], pl[t][1]);
        split2h(acc[2 * t + 1][0], acc[2 * t + 1][1], ph[t][2], pl[t][2]);
        split2h(acc[2 * t + 1][2], acc[2 * t + 1][3], ph[t][3], pl[t][3]);
    }

    // ---- O = P V : 2-term (Ph + Pl) x Vhi ----
    float oacc[8][4];
#pragma unroll
    for (int nd = 0; nd < 8; nd++)
#pragma unroll
        for (int v = 0; v < 4; v++) oacc[nd][v] = 0.f;

    auto pv_chunk = [&](uint32_t bufoff, int ktb) {
        uint32_t vbase = smb + (uint32_t)(bufoff + (lane & 15) * QSTR + (lane >> 4) * 8) * 2;
#pragma unroll
        for (int ktl = 0; ktl < 8; ktl++) {
            int kt = ktb + ktl;
            uint32_t vrow = vbase + (uint32_t)(ktl * 16 * QSTR) * 2;
#pragma unroll
            for (int ndp = 0; ndp < 4; ndp++) {
                uint32_t vh4[4];
                ldmx4t(vh4, vrow + ndp * 32);
                mma_f32(oacc[2 * ndp],     ph[kt][0], ph[kt][1], ph[kt][2], ph[kt][3], vh4[0], vh4[1]);
                mma_f32(oacc[2 * ndp],     pl[kt][0], pl[kt][1], pl[kt][2], pl[kt][3], vh4[0], vh4[1]);
                mma_f32(oacc[2 * ndp + 1], ph[kt][0], ph[kt][1], ph[kt][2], ph[kt][3], vh4[2], vh4[3]);
                mma_f32(oacc[2 * ndp + 1], pl[kt][0], pl[kt][1], pl[kt][2], pl[kt][3], vh4[2], vh4[3]);
            }
        }
    };

    cp_wait<1>();                  // V0 arrived
    __syncthreads();
    pv_chunk(AT_BUF0, 0);
    cp_wait<0>();                  // V1 arrived
    __syncthreads();
    pv_chunk(AT_BUF1, 8);

    // ---- write O as fp16 hi/lo ----
    {
        size_t row0 = (size_t)(b * NMM + q0 + wid * 16 + lr);
        __half* oh0 = Ohi + row0 * DIM + h * HD + 2 * lc;
        __half* ol0 = Olo + row0 * DIM + h * HD + 2 * lc;
        __half* oh1 = oh0 + (size_t)8 * DIM;
        __half* ol1 = ol0 + (size_t)8 * DIM;
#pragma unroll
        for (int nd = 0; nd < 8; nd++) {
            uint32_t hh, ll;
            split2h(oacc[nd][0], oacc[nd][1], hh, ll);
            *(uint32_t*)(oh0 + nd * 8) = hh;
            *(uint32_t*)(ol0 + nd * 8) = ll;
            split2h(oacc[nd][2], oacc[nd][3], hh, ll);
            *(uint32_t*)(oh1 + nd * 8) = hh;
            *(uint32_t*)(ol1 + nd * 8) = ll;
        }
    }
}

// ---------------------------------------------------------------------------
extern "C" void kernel_launch(void* const* d_in, const int* in_sizes, int n_in,
                              void* d_out, int out_size)
{
    const float* xmm   = (const float*)d_in[0];
    const float* xv    = (const float*)d_in[1];
    const float* xa    = (const float*)d_in[2];
    const float* Wq    = (const float*)d_in[3];
    const float* Wkv   = (const float*)d_in[4];
    const float* Wproj = (const float*)d_in[5];
    const float* bproj = (const float*)d_in[6];

    float* out = (float*)d_out;

    float* attn_fb;
    cudaGetSymbolAddress((void**)&attn_fb, g_attn_fallback);

    __half *Axh, *Axl, *Ash, *Asl;
    __half *Qh, *Ql, *KVh, *KVl, *Oh, *Ol;
    __half *Wqt, *Wkt, *Wpt;
    cudaGetSymbolAddress((void**)&Axh, g_Axmm_hi);
    cudaGetSymbolAddress((void**)&Axl, g_Axmm_lo);
    cudaGetSymbolAddress((void**)&Ash, g_Asrc_hi);
    cudaGetSymbolAddress((void**)&Asl, g_Asrc_lo);
    cudaGetSymbolAddress((void**)&Qh,  g_Qh);
    cudaGetSymbolAddress((void**)&Ql,  g_Ql);
    cudaGetSymbolAddress((void**)&KVh, g_KVh);
    cudaGetSymbolAddress((void**)&KVl, g_KVl);
    cudaGetSymbolAddress((void**)&Oh,  g_Oh);
    cudaGetSymbolAddress((void**)&Ol,  g_Ol);
    cudaGetSymbolAddress((void**)&Wqt, g_Wqt);
    cudaGetSymbolAddress((void**)&Wkt, g_Wkvt);
    cudaGetSymbolAddress((void**)&Wpt, g_Wpt);

    const size_t out_elems  = (size_t)MQ * DIM;
    const size_t attn_elems = (size_t)BS * HEADS * NMM * NSRC;
    float* attn_out = ((size_t)out_size >= out_elems + attn_elems)
                        ? out + out_elems : attn_fb;

    cudaFuncSetAttribute(gemm_qkv,  cudaFuncAttributeMaxDynamicSharedMemorySize, GEMM_SMEM);
    cudaFuncSetAttribute(gemm_proj, cudaFuncAttributeMaxDynamicSharedMemorySize, GEMM_SMEM);
    cudaFuncSetAttribute(attn_mma,  cudaFuncAttributeMaxDynamicSharedMemorySize, AT_SMEM_BYTES);

    // --- conversions ---
    {
        dim3 bb(32, 8);
        transpose_all<<<dim3(2 * DIM / 32, DIM / 32, 3), bb>>>(
            Wq, Wqt, Wkv, Wkt, Wproj, Wpt);
    }
    split_all_v4<<<dim3(1024, 2), 256>>>((const float4*)xmm,
                                         (const float4*)xv, (const float4*)xa,
                                         (uint2*)Axh, (uint2*)Axl,
                                         (uint2*)Ash, (uint2*)Asl);

    // --- fused Q + KV projection ---
    gemm_qkv<<<dim3(3 * DIM / 128, MQ / 128), 256, GEMM_SMEM>>>(
        Axh, Axl, Wqt, Qh, Ql,
        Ash, Asl, Wkt, KVh, KVl);
    // --- attention ---
    attn_mma<<<dim3(NMM / 128, HEADS, BS), 256, AT_SMEM_BYTES>>>(
        Qh, Ql, KVh, KVl, attn_out, Oh, Ol);
    // --- out = O @ Wproj + bproj (fp32) ---
    gemm_proj<<<dim3(DIM / 128, MQ / 128), 256, GEMM_SMEM>>>(
        Oh, Ol, Wpt, out, bproj);
}